// round 12
// baseline (speedup 1.0000x reference)
#include <cuda_runtime.h>
#include <cuda_bf16.h>
#include <math.h>
#include <stdint.h>

#define B_    8
#define L_    2048
#define D_    256
#define N_    16
#define R_    16
#define CL    32          // scan chunk length
#define NC    (L_/CL)     // 64 chunks
#define SEGC  (NC/4)      // 16 chunks per combine segment

typedef unsigned long long ull;

// ---------------- scratch (device globals) ----------------
__device__ float    g_delta  [B_*L_*D_];      // slow-path only
__device__ float    g_C      [B_*L_*16];      // C projections (for correct2)
__device__ float    g_pc     [B_*L_*D_];      // cumulative p1 within chunk
__device__ float    g_P      [B_*NC*N_*D_];
__device__ float    g_H      [B_*NC*N_*D_];
__device__ float    g_hs     [B_*NC*N_*D_];
__device__ float    g_y      [B_*L_*D_];      // y_local (pre-correction)
__device__ uint32_t g_y16    [B_*L_*D_];      // final y packed (bf16 hi | lo<<16)
__device__ uint32_t g_W16    [D_*D_];         // W_out packed (bf16 hi | lo<<16)

__device__ __forceinline__ float softplusf(float v) {
    return v > 20.0f ? v : __logf(1.0f + __expf(v));
}

__device__ __forceinline__ uint32_t pack_hilo(float v) {
    __nv_bfloat16 h = __float2bfloat16(v);
    __nv_bfloat16 l = __float2bfloat16(v - __bfloat162float(h));
    return (uint32_t)__bfloat16_as_ushort(h) |
           ((uint32_t)__bfloat16_as_ushort(l) << 16);
}

// ---------------- packed f32x2 helpers ----------------
__device__ __forceinline__ ull pack2(float lo, float hi) {
    ull r;
    asm("mov.b64 %0, {%1, %2};" : "=l"(r) : "f"(lo), "f"(hi));
    return r;
}
__device__ __forceinline__ void unpack2(ull v, float& lo, float& hi) {
    asm("mov.b64 {%0, %1}, %2;" : "=f"(lo), "=f"(hi) : "l"(v));
}
__device__ __forceinline__ ull mul2(ull a, ull b) {
    ull d;
    asm("mul.rn.f32x2 %0, %1, %2;" : "=l"(d) : "l"(a), "l"(b));
    return d;
}
__device__ __forceinline__ ull fma2(ull a, ull b, ull c) {
    ull d;
    asm("fma.rn.f32x2 %0, %1, %2, %3;" : "=l"(d) : "l"(a), "l"(b), "l"(c));
    return d;
}
__device__ __forceinline__ void powers16_p2(float p1, ull e2[8]) {
    const float p1sq = p1 * p1;
    e2[0] = pack2(p1, p1sq);
    const ull pstep = pack2(p1sq, p1sq);
    #pragma unroll
    for (int k = 1; k < 8; ++k) e2[k] = mul2(e2[k-1], pstep);
}

__device__ __forceinline__ float check_A(const float* __restrict__ A_log,
                                         int d, bool& fast) {
    float a0 = -__expf(__ldg(A_log + d*N_));
    fast = true;
    #pragma unroll
    for (int n = 1; n < N_; ++n) {
        float an = -__expf(__ldg(A_log + d*N_ + n));
        fast = fast && (fabsf(an - a0*(float)(n+1)) <= 1e-4f*(float)(n+1));
    }
    return a0;
}

// ---------------------------------------------------------------------------
// Kernel 1 (FUSED): W pack + projections + local scan for a mirror chunk pair.
// Block = (b, pair c / c'=NC-1-c). 64 rows: [0:32)=chunk c, [32:64)=chunk c'.
// smem: sx[64][256] fp32 x rows; sp[64][80] projections.
//   sp cols: [0:16)=delta_r, [16:32)=Bf, [32:48)=Bb, [48:64)=C, [64:80)=xb-proj.
// ---------------------------------------------------------------------------
__global__ __launch_bounds__(256, 2) void fps_kernel(
    const float* __restrict__ x, const float* __restrict__ Wxp,
    const float* __restrict__ Wxb, const float* __restrict__ Wdt,
    const float* __restrict__ bdt, const float* __restrict__ A_log,
    const float* __restrict__ Dskip, const float* __restrict__ Wout)
{
    extern __shared__ __align__(16) float fsm[];
    float* sx = fsm;                // [64][256]  64 KB
    float* sp = fsm + 64*256;       // [64][80]   20 KB

    const int bp = blockIdx.x;      // 0 .. B_*NC/2-1 = 255
    const int b  = bp >> 5;         // NC/2 = 32 pairs
    const int c  = bp & 31;
    const int cp = NC - 1 - c;
    const int tid = threadIdx.x;

    // Phase 0: pack 256 W_out elements per block (covers all 65536).
    g_W16[bp*256 + tid] = pack_hilo(Wout[bp*256 + tid]);

    // Phase 1: load 64 x rows (chunk c then chunk c')
    for (int i = tid; i < 64*256; i += 256) {
        const int r = i >> 8, col = i & 255;
        const int l = (r < 32) ? c*CL + r : cp*CL + (r - 32);
        sx[i] = x[(b*L_ + l)*D_ + col];
    }
    __syncthreads();

    // Phase 2: stage A — 80 projections x 64 rows (8 warps x 10 outputs).
    // Lane owns 8 consecutive K elements -> LDS.128 loads.
    {
        const int warp = tid >> 5, lane = tid & 31;
        #pragma unroll
        for (int t = 0; t < 10; ++t) {
            const int j = warp + 8*t;
            const float* Wrow = (j < 64) ? (Wxp + j*D_) : (Wxb + (j-64)*D_);
            const float4 w0 = __ldg(reinterpret_cast<const float4*>(Wrow) + lane*2);
            const float4 w1 = __ldg(reinterpret_cast<const float4*>(Wrow) + lane*2 + 1);
            for (int r = 0; r < 64; ++r) {
                const float4* s4 = reinterpret_cast<const float4*>(sx + r*256) + lane*2;
                const float4 a0 = s4[0], a1 = s4[1];
                float acc = a0.x*w0.x + a0.y*w0.y;
                acc = fmaf(a0.z, w0.z, acc);
                acc = fmaf(a0.w, w0.w, acc);
                acc = fmaf(a1.x, w1.x, acc);
                acc = fmaf(a1.y, w1.y, acc);
                acc = fmaf(a1.z, w1.z, acc);
                acc = fmaf(a1.w, w1.w, acc);
                #pragma unroll
                for (int o = 16; o; o >>= 1)
                    acc += __shfl_xor_sync(0xffffffffu, acc, o);
                if (lane == 0) sp[r*80 + j] = acc;
            }
        }
    }
    __syncthreads();

    // Phase 3: write C projections for correct2
    for (int i = tid; i < 64*16; i += 256) {
        const int r = i >> 4, jj = i & 15;
        const int l = (r < 32) ? c*CL + r : cp*CL + (r - 32);
        g_C[(b*L_ + l)*16 + jj] = sp[r*80 + 48 + jj];
    }

    // Phase 4: per-channel scan over both chunks
    const int d = tid;
    float wdt[R_];
    #pragma unroll
    for (int q = 0; q < R_; ++q) wdt[q] = __ldg(Wdt + d*R_ + q);
    const float bv  = bdt[d];
    const float dsk = Dskip[d];
    bool fast;
    const float a0 = check_A(A_log, d, fast);

    #pragma unroll 1
    for (int sel = 0; sel < 2; ++sel) {
        const int rb = sel * 32;
        const int cc = sel ? cp : c;
        const int l0 = cc * CL;

        float* y_ptr  = g_y  + (b*L_ + l0)*D_ + d;
        float* pc_ptr = g_pc + (b*L_ + l0)*D_ + d;
        float* Pp = g_P + ((b*NC + cc)*N_)*D_ + d;
        float* Hp = g_H + ((b*NC + cc)*N_)*D_ + d;

        if (fast) {
            ull h2[8];
            #pragma unroll
            for (int k = 0; k < 8; ++k) h2[k] = 0ull;
            float p1 = 1.f;

            #pragma unroll 2
            for (int t = 0; t < CL; ++t) {
                const int rowA = rb + t;
                const int rowB = sel ? (31 - t) : (63 - t);

                // dt dots via float4 loads (4 partial sums each)
                const float4* qa = reinterpret_cast<const float4*>(&sp[rowA*80]);
                const float4* qb = reinterpret_cast<const float4*>(&sp[rowB*80 + 64]);
                float s0 = bv, s1 = 0.f, s2 = 0.f, s3 = 0.f;
                float u0 = bv, u1 = 0.f, u2 = 0.f, u3 = 0.f;
                #pragma unroll
                for (int q4 = 0; q4 < 4; ++q4) {
                    const float4 av = qa[q4], bw = qb[q4];
                    s0 = fmaf(av.x, wdt[4*q4    ], s0);
                    s1 = fmaf(av.y, wdt[4*q4 + 1], s1);
                    s2 = fmaf(av.z, wdt[4*q4 + 2], s2);
                    s3 = fmaf(av.w, wdt[4*q4 + 3], s3);
                    u0 = fmaf(bw.x, wdt[4*q4    ], u0);
                    u1 = fmaf(bw.y, wdt[4*q4 + 1], u1);
                    u2 = fmaf(bw.z, wdt[4*q4 + 2], u2);
                    u3 = fmaf(bw.w, wdt[4*q4 + 3], u3);
                }
                const float dl  = softplusf((s0 + s1) + (s2 + s3));
                const float dlb = softplusf((u0 + u1) + (u2 + u3));

                const float xv = sx[rowA*256 + d];
                const float xr = sx[rowB*256 + d];

                const float e1 = __expf(dl * a0);
                const float e1sq = e1 * e1;
                ull e = pack2(e1, e1sq);
                const ull estep = pack2(e1sq, e1sq);
                const float c1 = dl * xv, c2 = dlb * xr;
                const ull c1p = pack2(c1, c1);
                const ull c2p = pack2(c2, c2);
                ull y2 = 0ull;
                const ulonglong2* Bf4 = reinterpret_cast<const ulonglong2*>(&sp[rowA*80 + 16]);
                const ulonglong2* Bb4 = reinterpret_cast<const ulonglong2*>(&sp[rowA*80 + 32]);
                const ulonglong2* C4  = reinterpret_cast<const ulonglong2*>(&sp[rowA*80 + 48]);
                #pragma unroll
                for (int k4 = 0; k4 < 4; ++k4) {
                    const ulonglong2 bf = Bf4[k4];
                    const ulonglong2 bb = Bb4[k4];
                    const ulonglong2 cv = C4[k4];
                    ull du = fma2(c1p, bf.x, mul2(c2p, bb.x));
                    h2[2*k4] = fma2(e, h2[2*k4], du);
                    y2 = fma2(h2[2*k4], cv.x, y2);
                    e = mul2(e, estep);
                    du = fma2(c1p, bf.y, mul2(c2p, bb.y));
                    h2[2*k4+1] = fma2(e, h2[2*k4+1], du);
                    y2 = fma2(h2[2*k4+1], cv.y, y2);
                    if (k4 < 3) e = mul2(e, estep);
                }
                p1 *= e1;
                float ylo, yhi; unpack2(y2, ylo, yhi);
                y_ptr [t*D_] = fmaf(xv + xr, dsk, ylo + yhi);
                pc_ptr[t*D_] = p1;
            }
            ull pw2[8]; powers16_p2(p1, pw2);
            #pragma unroll
            for (int k = 0; k < 8; ++k) {
                float plo, phi; unpack2(pw2[k], plo, phi);
                float hlo, hhi; unpack2(h2[k], hlo, hhi);
                Pp[(2*k  )*D_] = plo;  Pp[(2*k+1)*D_] = phi;
                Hp[(2*k  )*D_] = hlo;  Hp[(2*k+1)*D_] = hhi;
            }
        } else {
            float h[N_], a[N_], p[N_];
            #pragma unroll
            for (int n = 0; n < N_; ++n) {
                a[n] = -__expf(__ldg(A_log + d*N_ + n));
                p[n] = 1.f;
                h[n] = 0.f;
            }
            for (int t = 0; t < CL; ++t) {
                const int rowA = rb + t;
                const int rowB = sel ? (31 - t) : (63 - t);
                float s = bv, sb = bv;
                #pragma unroll
                for (int q = 0; q < R_; ++q) {
                    s  = fmaf(sp[rowA*80 + q],      wdt[q], s);
                    sb = fmaf(sp[rowB*80 + 64 + q], wdt[q], sb);
                }
                const float dl  = softplusf(s);
                const float dlb = softplusf(sb);
                g_delta[(b*L_ + l0 + t)*D_ + d] = dl;   // for correct2 slow path
                const float xv = sx[rowA*256 + d];
                const float xr = sx[rowB*256 + d];
                const float c1 = dl*xv, c2 = dlb*xr;
                float y = 0.f;
                #pragma unroll
                for (int n = 0; n < N_; ++n) {
                    const float e = __expf(dl * a[n]);
                    h[n] = fmaf(e, h[n], fmaf(c1, sp[rowA*80 + 16 + n],
                                              c2 * sp[rowA*80 + 32 + n]));
                    y    = fmaf(h[n], sp[rowA*80 + 48 + n], y);
                    p[n] *= e;
                }
                y_ptr[t*D_] = fmaf(xv + xr, dsk, y);
            }
            #pragma unroll
            for (int n = 0; n < N_; ++n) { Pp[n*D_] = p[n]; Hp[n*D_] = h[n]; }
        }
    }
}

// ---------------------------------------------------------------------------
// Kernel 2: combine — segmented affine scan (unchanged).
// ---------------------------------------------------------------------------
__global__ __launch_bounds__(512) void combine_kernel()
{
    const int bn = blockIdx.x;          // 0..127
    const int b = bn >> 4;
    const int n = bn & 15;
    const int seg = threadIdx.x >> 7;   // 0..3
    const int dp  = threadIdx.x & 127;  // d-pair

    __shared__ ull sP[4][128];
    __shared__ ull sH[4][128];

    const ull* P2 = reinterpret_cast<const ull*>(g_P);
    const ull* H2 = reinterpret_cast<const ull*>(g_H);
    ull* hs2 = reinterpret_cast<ull*>(g_hs);

    const int c0 = seg * SEGC;
    #define CIDX(c) ((((b*NC + (c))*N_) + n)*128 + dp)

    ull Pc = pack2(1.f, 1.f), Hc = 0ull;
    #pragma unroll 4
    for (int i = 0; i < SEGC; ++i) {
        const int idx = CIDX(c0 + i);
        const ull p = P2[idx];
        Pc = mul2(p, Pc);
        Hc = fma2(p, Hc, H2[idx]);
    }
    sP[seg][dp] = Pc;
    sH[seg][dp] = Hc;
    __syncthreads();

    ull h = 0ull;
    #pragma unroll
    for (int t = 0; t < 3; ++t)
        if (t < seg) h = fma2(sP[t][dp], h, sH[t][dp]);

    #pragma unroll 4
    for (int i = 0; i < SEGC; ++i) {
        const int idx = CIDX(c0 + i);
        hs2[idx] = h;
        h = fma2(P2[idx], h, H2[idx]);
    }
    #undef CIDX
}

// ---------------------------------------------------------------------------
// Kernel 3: correct2 — y += pcum^n * hs * C; emits packed y16.
// sC rows loaded as 16B vectors.
// ---------------------------------------------------------------------------
__global__ __launch_bounds__(256) void correct2_kernel(
    const float* __restrict__ A_log)
{
    const int bc = blockIdx.x;
    const int b = bc / NC, c = bc - b*NC;
    const int d = threadIdx.x;
    const int l0 = c * CL;

    __shared__ __align__(16) float sC[CL][N_];
    for (int i = d; i < CL*N_; i += 256) {
        int t = i >> 4, j = i & 15;
        sC[t][j] = g_C[(b*L_ + l0 + t)*16 + j];
    }
    __syncthreads();

    bool fast;
    const float a0 = check_A(A_log, d, fast);
    (void)a0;

    const float* y_ptr  = g_y  + (b*L_ + l0)*D_ + d;
    uint32_t* y16_ptr   = g_y16 + (b*L_ + l0)*D_ + d;
    const float* pc_ptr = g_pc + (b*L_ + l0)*D_ + d;

    if (fast) {
        ull q2[8];
        #pragma unroll
        for (int k = 0; k < 8; ++k) {
            const float qlo = g_hs[((b*NC + c)*N_ + 2*k  )*D_ + d];
            const float qhi = g_hs[((b*NC + c)*N_ + 2*k+1)*D_ + d];
            q2[k] = pack2(qlo, qhi);
        }
        #pragma unroll
        for (int t0 = 0; t0 < CL; t0 += 4) {
            float p1[4], yl[4];
            #pragma unroll
            for (int i = 0; i < 4; ++i) {
                p1[i] = pc_ptr[(t0+i)*D_];
                yl[i] = y_ptr [(t0+i)*D_];
            }
            #pragma unroll
            for (int i = 0; i < 4; ++i) {
                const int t = t0 + i;
                const float psq = p1[i] * p1[i];
                ull pw = pack2(p1[i], psq);
                const ull pstep = pack2(psq, psq);
                const ulonglong2* C4 = reinterpret_cast<const ulonglong2*>(&sC[t][0]);
                ull corr2 = 0ull;
                #pragma unroll
                for (int k4 = 0; k4 < 4; ++k4) {
                    const ulonglong2 cv = C4[k4];
                    corr2 = fma2(mul2(pw, q2[2*k4]), cv.x, corr2);
                    pw = mul2(pw, pstep);
                    corr2 = fma2(mul2(pw, q2[2*k4+1]), cv.y, corr2);
                    if (k4 < 3) pw = mul2(pw, pstep);
                }
                float clo, chi; unpack2(corr2, clo, chi);
                y16_ptr[t*D_] = pack_hilo(yl[i] + clo + chi);
            }
        }
    } else {
        float q[N_];
        #pragma unroll
        for (int n = 0; n < N_; ++n)
            q[n] = g_hs[((b*NC + c)*N_ + n)*D_ + d];
        const float* dl_ptr = g_delta + (b*L_ + l0)*D_ + d;
        float a[N_];
        #pragma unroll
        for (int n = 0; n < N_; ++n)
            a[n] = -__expf(__ldg(A_log + d*N_ + n));
        for (int t = 0; t < CL; ++t) {
            const float dl = dl_ptr[t*D_];
            float corr = 0.f;
            #pragma unroll
            for (int n = 0; n < N_; ++n) {
                q[n] *= __expf(dl * a[n]);
                corr = fmaf(q[n], sC[t][n], corr);
            }
            y16_ptr[t*D_] = pack_hilo(y_ptr[t*D_] + corr);
        }
    }
}

// ---------------------------------------------------------------------------
// Kernel 4: out = y @ W_out^T via mma.sync bf16 split, prepacked (unchanged).
// ---------------------------------------------------------------------------
#define GP 72   // smem pitch in bf16 elements

__device__ __forceinline__ void mma_bf16(float dd[4],
                                         const uint32_t a[4],
                                         const uint32_t b[2]) {
    asm volatile(
        "mma.sync.aligned.m16n8k16.row.col.f32.bf16.bf16.f32 "
        "{%0,%1,%2,%3}, {%4,%5,%6,%7}, {%8,%9}, {%0,%1,%2,%3};"
        : "+f"(dd[0]), "+f"(dd[1]), "+f"(dd[2]), "+f"(dd[3])
        : "r"(a[0]), "r"(a[1]), "r"(a[2]), "r"(a[3]), "r"(b[0]), "r"(b[1]));
}

__global__ __launch_bounds__(256) void gemm_mma_kernel(float* __restrict__ out)
{
    extern __shared__ __nv_bfloat16 sm[];
    __nv_bfloat16* sA_hi = sm;                 // [128][GP]
    __nv_bfloat16* sA_lo = sm + 128*GP;
    __nv_bfloat16* sB_hi = sm + 2*128*GP;
    __nv_bfloat16* sB_lo = sm + 3*128*GP;

    const int tid  = threadIdx.x;
    const int wid  = tid >> 5;
    const int lane = tid & 31;
    const int gid  = lane >> 2;
    const int t4   = lane & 3;

    const int j0 = blockIdx.x * 128;
    const int m0 = blockIdx.y * 128;
    const int wm = (wid >> 2) * 64;
    const int wn = (wid & 3) * 32;

    float acc[4][4][4];
    #pragma unroll
    for (int i = 0; i < 4; ++i)
        #pragma unroll
        for (int j = 0; j < 4; ++j)
            #pragma unroll
            for (int q = 0; q < 4; ++q) acc[i][j][q] = 0.f;

    const int lrow = tid >> 5;
    const int lpc  = tid & 31;

    for (int kc = 0; kc < 256; kc += 64) {
        __syncthreads();
        #pragma unroll
        for (int rr = 0; rr < 16; ++rr) {
            const int row = lrow + rr*8;
            const int soff = row*GP + lpc*2;

            const uint2 wa = *reinterpret_cast<const uint2*>(
                g_y16 + (m0 + row)*D_ + kc + lpc*2);
            *reinterpret_cast<uint32_t*>(sA_hi + soff) = __byte_perm(wa.x, wa.y, 0x5410);
            *reinterpret_cast<uint32_t*>(sA_lo + soff) = __byte_perm(wa.x, wa.y, 0x7632);

            const uint2 wb = *reinterpret_cast<const uint2*>(
                g_W16 + (j0 + row)*D_ + kc + lpc*2);
            *reinterpret_cast<uint32_t*>(sB_hi + soff) = __byte_perm(wb.x, wb.y, 0x5410);
            *reinterpret_cast<uint32_t*>(sB_lo + soff) = __byte_perm(wb.x, wb.y, 0x7632);
        }
        __syncthreads();

        #pragma unroll
        for (int ks = 0; ks < 4; ++ks) {
            const int k0 = ks*16;
            uint32_t a_hi[4][4], a_lo[4][4], b_hi[4][2], b_lo[4][2];

            #pragma unroll
            for (int mf = 0; mf < 4; ++mf) {
                const int r0 = wm + mf*16 + gid;
                const int c0 = k0 + t4*2;
                a_hi[mf][0] = *reinterpret_cast<const uint32_t*>(sA_hi + (r0    )*GP + c0    );
                a_hi[mf][1] = *reinterpret_cast<const uint32_t*>(sA_hi + (r0 + 8)*GP + c0    );
                a_hi[mf][2] = *reinterpret_cast<const uint32_t*>(sA_hi + (r0    )*GP + c0 + 8);
                a_hi[mf][3] = *reinterpret_cast<const uint32_t*>(sA_hi + (r0 + 8)*GP + c0 + 8);
                a_lo[mf][0] = *reinterpret_cast<const uint32_t*>(sA_lo + (r0    )*GP + c0    );
                a_lo[mf][1] = *reinterpret_cast<const uint32_t*>(sA_lo + (r0 + 8)*GP + c0    );
                a_lo[mf][2] = *reinterpret_cast<const uint32_t*>(sA_lo + (r0    )*GP + c0 + 8);
                a_lo[mf][3] = *reinterpret_cast<const uint32_t*>(sA_lo + (r0 + 8)*GP + c0 + 8);
            }
            #pragma unroll
            for (int nf = 0; nf < 4; ++nf) {
                const int nr = wn + nf*8 + gid;
                const int c0 = k0 + t4*2;
                b_hi[nf][0] = *reinterpret_cast<const uint32_t*>(sB_hi + nr*GP + c0    );
                b_hi[nf][1] = *reinterpret_cast<const uint32_t*>(sB_hi + nr*GP + c0 + 8);
                b_lo[nf][0] = *reinterpret_cast<const uint32_t*>(sB_lo + nr*GP + c0    );
                b_lo[nf][1] = *reinterpret_cast<const uint32_t*>(sB_lo + nr*GP + c0 + 8);
            }

            #pragma unroll
            for (int mf = 0; mf < 4; ++mf)
                #pragma unroll
                for (int nf = 0; nf < 4; ++nf) {
                    mma_bf16(acc[mf][nf], a_hi[mf], b_hi[nf]);
                    mma_bf16(acc[mf][nf], a_hi[mf], b_lo[nf]);
                    mma_bf16(acc[mf][nf], a_lo[mf], b_hi[nf]);
                }
        }
    }

    #pragma unroll
    for (int mf = 0; mf < 4; ++mf) {
        const int mrow = m0 + wm + mf*16 + gid;
        #pragma unroll
        for (int nf = 0; nf < 4; ++nf) {
            const int ncol = j0 + wn + nf*8 + t4*2;
            *reinterpret_cast<float2*>(out + (size_t)mrow*D_ + ncol) =
                make_float2(acc[mf][nf][0], acc[mf][nf][1]);
            *reinterpret_cast<float2*>(out + (size_t)(mrow + 8)*D_ + ncol) =
                make_float2(acc[mf][nf][2], acc[mf][nf][3]);
        }
    }
}

// ---------------------------------------------------------------------------
extern "C" void kernel_launch(void* const* d_in, const int* in_sizes, int n_in,
                              void* d_out, int out_size)
{
    const float* x     = (const float*)d_in[0];
    const float* Wxp   = (const float*)d_in[1];
    const float* Wxb   = (const float*)d_in[2];
    const float* Wdt   = (const float*)d_in[3];
    const float* bdt   = (const float*)d_in[4];
    const float* A_log = (const float*)d_in[5];
    const float* Dskip = (const float*)d_in[6];
    const float* Wout  = (const float*)d_in[7];
    float* out = (float*)d_out;

    const int GEMM_SMEM = 4 * 128 * GP * (int)sizeof(__nv_bfloat16);  // 73728 B
    const int FPS_SMEM  = (64*256 + 64*80) * (int)sizeof(float);      // 86016 B
    cudaFuncSetAttribute(gemm_mma_kernel,
                         cudaFuncAttributeMaxDynamicSharedMemorySize, GEMM_SMEM);
    cudaFuncSetAttribute(fps_kernel,
                         cudaFuncAttributeMaxDynamicSharedMemorySize, FPS_SMEM);

    fps_kernel     <<<B_*(NC/2), 256, FPS_SMEM>>>(x, Wxp, Wxb, Wdt, bdt,
                                                  A_log, Dskip, Wout);
    combine_kernel <<<B_*N_, 512>>>();
    correct2_kernel<<<B_*NC, 256>>>(A_log);
    gemm_mma_kernel<<<dim3(2, 128), 256, GEMM_SMEM>>>(out);
}

// round 13
// speedup vs baseline: 1.1509x; 1.1509x over previous
#include <cuda_runtime.h>
#include <cuda_bf16.h>
#include <math.h>
#include <stdint.h>

#define B_    8
#define L_    2048
#define D_    256
#define N_    16
#define R_    16
#define CL    32          // scan chunk length
#define NC    (L_/CL)     // 64 chunks
#define SEGC  (NC/4)      // 16 chunks per combine segment
#define NP    80          // projection outputs per row

typedef unsigned long long ull;

// ---------------- scratch (device globals) ----------------
__device__ float    g_P80    [B_*L_*NP];      // all projections (from tensor GEMM)
__device__ float    g_delta  [B_*L_*D_];      // slow-path only
__device__ float    g_pc     [B_*L_*D_];      // cumulative p1 within chunk
__device__ float    g_P      [B_*NC*N_*D_];
__device__ float    g_H      [B_*NC*N_*D_];
__device__ float    g_hs     [B_*NC*N_*D_];
__device__ float    g_y      [B_*L_*D_];      // y_local (pre-correction)
__device__ uint32_t g_y16    [B_*L_*D_];      // final y packed (bf16 hi | lo<<16)
__device__ uint32_t g_W16    [D_*D_];         // W_out packed (bf16 hi | lo<<16)
__device__ uint32_t g_Wall16 [128*D_];        // [Wxp(64);Wxb(16);0(48)] packed

__device__ __forceinline__ float softplusf(float v) {
    return v > 20.0f ? v : log1pf(__expf(v));
}

__device__ __forceinline__ uint32_t pack_hilo(float v) {
    __nv_bfloat16 h = __float2bfloat16(v);
    __nv_bfloat16 l = __float2bfloat16(v - __bfloat162float(h));
    return (uint32_t)__bfloat16_as_ushort(h) |
           ((uint32_t)__bfloat16_as_ushort(l) << 16);
}

// ---------------- packed f32x2 helpers ----------------
__device__ __forceinline__ ull pack2(float lo, float hi) {
    ull r;
    asm("mov.b64 %0, {%1, %2};" : "=l"(r) : "f"(lo), "f"(hi));
    return r;
}
__device__ __forceinline__ void unpack2(ull v, float& lo, float& hi) {
    asm("mov.b64 {%0, %1}, %2;" : "=f"(lo), "=f"(hi) : "l"(v));
}
__device__ __forceinline__ ull mul2(ull a, ull b) {
    ull d;
    asm("mul.rn.f32x2 %0, %1, %2;" : "=l"(d) : "l"(a), "l"(b));
    return d;
}
__device__ __forceinline__ ull fma2(ull a, ull b, ull c) {
    ull d;
    asm("fma.rn.f32x2 %0, %1, %2, %3;" : "=l"(d) : "l"(a), "l"(b), "l"(c));
    return d;
}
__device__ __forceinline__ void powers16_p2(float p1, ull e2[8]) {
    const float p1sq = p1 * p1;
    e2[0] = pack2(p1, p1sq);
    const ull pstep = pack2(p1sq, p1sq);
    #pragma unroll
    for (int k = 1; k < 8; ++k) e2[k] = mul2(e2[k-1], pstep);
}

__device__ __forceinline__ float check_A(const float* __restrict__ A_log,
                                         int d, bool& fast) {
    float a0 = -__expf(__ldg(A_log + d*N_));
    fast = true;
    #pragma unroll
    for (int n = 1; n < N_; ++n) {
        float an = -__expf(__ldg(A_log + d*N_ + n));
        fast = fast && (fabsf(an - a0*(float)(n+1)) <= 1e-4f*(float)(n+1));
    }
    return a0;
}

// ---------------------------------------------------------------------------
// Kernel 0: pack W_out (65536) + Wall (128x256, zero-padded) to bf16 hi/lo.
// grid = 384 blocks x 256.
// ---------------------------------------------------------------------------
__global__ __launch_bounds__(256) void pack_kernel(
    const float* __restrict__ Wout, const float* __restrict__ Wxp,
    const float* __restrict__ Wxb)
{
    const int i = blockIdx.x*256 + threadIdx.x;
    if (i < D_*D_) {
        g_W16[i] = pack_hilo(Wout[i]);
    } else {
        const int k = i - D_*D_;        // 0 .. 32767
        const int row = k >> 8, col = k & 255;
        float v = 0.f;
        if (row < 64)       v = Wxp[row*D_ + col];
        else if (row < 80)  v = Wxb[(row - 64)*D_ + col];
        g_Wall16[k] = pack_hilo(v);
    }
}

// ---------------------------------------------------------------------------
// Kernel 1: projgemm — P80 = x @ Wall^T via mma.sync bf16 split.
// CTA tile 128(M) x 128(N), grid (1, 128). A cvt on the fly; B prepacked.
// Epilogue writes only cols < 80 into g_P80 (row stride 80, fp32).
// ---------------------------------------------------------------------------
#define GP 72   // smem pitch in bf16 elements

__device__ __forceinline__ void mma_bf16(float dd[4],
                                         const uint32_t a[4],
                                         const uint32_t b[2]) {
    asm volatile(
        "mma.sync.aligned.m16n8k16.row.col.f32.bf16.bf16.f32 "
        "{%0,%1,%2,%3}, {%4,%5,%6,%7}, {%8,%9}, {%0,%1,%2,%3};"
        : "+f"(dd[0]), "+f"(dd[1]), "+f"(dd[2]), "+f"(dd[3])
        : "r"(a[0]), "r"(a[1]), "r"(a[2]), "r"(a[3]), "r"(b[0]), "r"(b[1]));
}

__global__ __launch_bounds__(256) void projgemm_kernel(const float* __restrict__ x)
{
    extern __shared__ __nv_bfloat16 sm[];
    __nv_bfloat16* sA_hi = sm;
    __nv_bfloat16* sA_lo = sm + 128*GP;
    __nv_bfloat16* sB_hi = sm + 2*128*GP;
    __nv_bfloat16* sB_lo = sm + 3*128*GP;

    const int tid  = threadIdx.x;
    const int wid  = tid >> 5;
    const int lane = tid & 31;
    const int gid  = lane >> 2;
    const int t4   = lane & 3;

    const int m0 = blockIdx.y * 128;
    const int wm = (wid >> 2) * 64;
    const int wn = (wid & 3) * 32;

    float acc[4][4][4];
    #pragma unroll
    for (int i = 0; i < 4; ++i)
        #pragma unroll
        for (int j = 0; j < 4; ++j)
            #pragma unroll
            for (int q = 0; q < 4; ++q) acc[i][j][q] = 0.f;

    const int lrow = tid >> 5;
    const int lpc  = tid & 31;

    for (int kc = 0; kc < 256; kc += 64) {
        __syncthreads();
        #pragma unroll
        for (int rr = 0; rr < 16; ++rr) {
            const int row = lrow + rr*8;
            const int soff = row*GP + lpc*2;

            const float2 va = *reinterpret_cast<const float2*>(
                x + (size_t)(m0 + row)*D_ + kc + lpc*2);
            __nv_bfloat16 ahx = __float2bfloat16(va.x);
            __nv_bfloat16 ahy = __float2bfloat16(va.y);
            __nv_bfloat16 alx = __float2bfloat16(va.x - __bfloat162float(ahx));
            __nv_bfloat16 aly = __float2bfloat16(va.y - __bfloat162float(ahy));
            *reinterpret_cast<__nv_bfloat162*>(sA_hi + soff) = __nv_bfloat162(ahx, ahy);
            *reinterpret_cast<__nv_bfloat162*>(sA_lo + soff) = __nv_bfloat162(alx, aly);

            const uint2 wb = *reinterpret_cast<const uint2*>(
                g_Wall16 + row*D_ + kc + lpc*2);
            *reinterpret_cast<uint32_t*>(sB_hi + soff) = __byte_perm(wb.x, wb.y, 0x5410);
            *reinterpret_cast<uint32_t*>(sB_lo + soff) = __byte_perm(wb.x, wb.y, 0x7632);
        }
        __syncthreads();

        #pragma unroll
        for (int ks = 0; ks < 4; ++ks) {
            const int k0 = ks*16;
            uint32_t a_hi[4][4], a_lo[4][4], b_hi[4][2], b_lo[4][2];

            #pragma unroll
            for (int mf = 0; mf < 4; ++mf) {
                const int r0 = wm + mf*16 + gid;
                const int c0 = k0 + t4*2;
                a_hi[mf][0] = *reinterpret_cast<const uint32_t*>(sA_hi + (r0    )*GP + c0    );
                a_hi[mf][1] = *reinterpret_cast<const uint32_t*>(sA_hi + (r0 + 8)*GP + c0    );
                a_hi[mf][2] = *reinterpret_cast<const uint32_t*>(sA_hi + (r0    )*GP + c0 + 8);
                a_hi[mf][3] = *reinterpret_cast<const uint32_t*>(sA_hi + (r0 + 8)*GP + c0 + 8);
                a_lo[mf][0] = *reinterpret_cast<const uint32_t*>(sA_lo + (r0    )*GP + c0    );
                a_lo[mf][1] = *reinterpret_cast<const uint32_t*>(sA_lo + (r0 + 8)*GP + c0    );
                a_lo[mf][2] = *reinterpret_cast<const uint32_t*>(sA_lo + (r0    )*GP + c0 + 8);
                a_lo[mf][3] = *reinterpret_cast<const uint32_t*>(sA_lo + (r0 + 8)*GP + c0 + 8);
            }
            #pragma unroll
            for (int nf = 0; nf < 4; ++nf) {
                const int nr = wn + nf*8 + gid;
                const int c0 = k0 + t4*2;
                b_hi[nf][0] = *reinterpret_cast<const uint32_t*>(sB_hi + nr*GP + c0    );
                b_hi[nf][1] = *reinterpret_cast<const uint32_t*>(sB_hi + nr*GP + c0 + 8);
                b_lo[nf][0] = *reinterpret_cast<const uint32_t*>(sB_lo + nr*GP + c0    );
                b_lo[nf][1] = *reinterpret_cast<const uint32_t*>(sB_lo + nr*GP + c0 + 8);
            }

            #pragma unroll
            for (int mf = 0; mf < 4; ++mf)
                #pragma unroll
                for (int nf = 0; nf < 4; ++nf) {
                    mma_bf16(acc[mf][nf], a_hi[mf], b_hi[nf]);
                    mma_bf16(acc[mf][nf], a_hi[mf], b_lo[nf]);
                    mma_bf16(acc[mf][nf], a_lo[mf], b_hi[nf]);
                }
        }
    }

    #pragma unroll
    for (int mf = 0; mf < 4; ++mf) {
        const int mrow = m0 + wm + mf*16 + gid;
        #pragma unroll
        for (int nf = 0; nf < 4; ++nf) {
            const int ncol = wn + nf*8 + t4*2;
            if (ncol < NP) {
                *reinterpret_cast<float2*>(g_P80 + (size_t)mrow*NP + ncol) =
                    make_float2(acc[mf][nf][0], acc[mf][nf][1]);
                *reinterpret_cast<float2*>(g_P80 + (size_t)(mrow + 8)*NP + ncol) =
                    make_float2(acc[mf][nf][2], acc[mf][nf][3]);
            }
        }
    }
}

// ---------------------------------------------------------------------------
// Kernel 2: scan — per chunk; dt-dots from staged P80, local recurrence.
// smem: sF[32][64] = P80[l][0:64]; sBb[32][16] = P80[L-1-l][64:80].
// ---------------------------------------------------------------------------
__global__ __launch_bounds__(256) void scan_kernel(
    const float* __restrict__ x, const float* __restrict__ Wdt,
    const float* __restrict__ bdt, const float* __restrict__ A_log,
    const float* __restrict__ Dskip)
{
    const int bc = blockIdx.x;
    const int b = bc / NC, c = bc - b*NC;
    const int d = threadIdx.x;
    const int l0 = c * CL;

    __shared__ __align__(16) float sF[CL][64];
    __shared__ __align__(16) float sBb[CL][16];

    for (int i = d; i < CL*64; i += 256) {
        const int r = i >> 6, col = i & 63;
        sF[r][col] = g_P80[(size_t)(b*L_ + l0 + r)*NP + col];
    }
    for (int i = d; i < CL*16; i += 256) {
        const int r = i >> 4, col = i & 15;
        sBb[r][col] = g_P80[(size_t)(b*L_ + (L_ - 1 - (l0 + r)))*NP + 64 + col];
    }
    __syncthreads();

    float wdt[R_];
    #pragma unroll
    for (int q = 0; q < R_; ++q) wdt[q] = __ldg(Wdt + d*R_ + q);
    const float bv  = bdt[d];
    const float dsk = Dskip[d];
    bool fast;
    const float a0 = check_A(A_log, d, fast);

    const float* x_ptr  = x + (b*L_ + l0)*D_ + d;
    const float* xr_ptr = x + (b*L_ + (L_ - 1 - l0))*D_ + d;
    float* y_ptr  = g_y  + (b*L_ + l0)*D_ + d;
    float* pc_ptr = g_pc + (b*L_ + l0)*D_ + d;
    float* Pp = g_P + ((b*NC + c)*N_)*D_ + d;
    float* Hp = g_H + ((b*NC + c)*N_)*D_ + d;

    if (fast) {
        ull h2[8];
        #pragma unroll
        for (int k = 0; k < 8; ++k) h2[k] = 0ull;
        float p1 = 1.f;

        #pragma unroll
        for (int t0 = 0; t0 < CL; t0 += 4) {
            float xv[4], xr[4];
            #pragma unroll
            for (int i = 0; i < 4; ++i) {
                xv[i] = x_ptr [(t0+i)*D_];
                xr[i] = xr_ptr[-(t0+i)*D_];
            }
            #pragma unroll
            for (int i = 0; i < 4; ++i) {
                const int t = t0 + i;
                // dt dots (float2 loads, two partial sums each)
                const float2* qa = reinterpret_cast<const float2*>(&sF[t][0]);
                const float2* qb = reinterpret_cast<const float2*>(&sBb[t][0]);
                float s0 = bv, s1 = 0.f, u0 = bv, u1 = 0.f;
                #pragma unroll
                for (int q = 0; q < 8; ++q) {
                    const float2 av = qa[q], bw = qb[q];
                    s0 = fmaf(av.x, wdt[2*q],   s0);
                    s1 = fmaf(av.y, wdt[2*q+1], s1);
                    u0 = fmaf(bw.x, wdt[2*q],   u0);
                    u1 = fmaf(bw.y, wdt[2*q+1], u1);
                }
                const float dl  = softplusf(s0 + s1);
                const float dlb = softplusf(u0 + u1);

                const float e1 = __expf(dl * a0);
                const float e1sq = e1 * e1;
                ull e = pack2(e1, e1sq);
                const ull estep = pack2(e1sq, e1sq);
                const float c1 = dl * xv[i], c2 = dlb * xr[i];
                const ull c1p = pack2(c1, c1);
                const ull c2p = pack2(c2, c2);
                ull y2 = 0ull;
                const ull* Bf2 = reinterpret_cast<const ull*>(&sF[t][16]);
                const ull* Bb2 = reinterpret_cast<const ull*>(&sF[t][32]);
                const ull* C2  = reinterpret_cast<const ull*>(&sF[t][48]);
                #pragma unroll
                for (int k = 0; k < 8; ++k) {
                    const ull du = fma2(c1p, Bf2[k], mul2(c2p, Bb2[k]));
                    h2[k] = fma2(e, h2[k], du);
                    y2    = fma2(h2[k], C2[k], y2);
                    if (k < 7) e = mul2(e, estep);
                }
                p1 *= e1;
                float ylo, yhi; unpack2(y2, ylo, yhi);
                y_ptr [t*D_] = fmaf(xv[i] + xr[i], dsk, ylo + yhi);
                pc_ptr[t*D_] = p1;
            }
        }
        ull pw2[8]; powers16_p2(p1, pw2);
        #pragma unroll
        for (int k = 0; k < 8; ++k) {
            float plo, phi; unpack2(pw2[k], plo, phi);
            float hlo, hhi; unpack2(h2[k], hlo, hhi);
            Pp[(2*k  )*D_] = plo;  Pp[(2*k+1)*D_] = phi;
            Hp[(2*k  )*D_] = hlo;  Hp[(2*k+1)*D_] = hhi;
        }
    } else {
        float h[N_], a[N_], p[N_];
        #pragma unroll
        for (int n = 0; n < N_; ++n) {
            a[n] = -__expf(__ldg(A_log + d*N_ + n));
            p[n] = 1.f;
            h[n] = 0.f;
        }
        for (int t = 0; t < CL; ++t) {
            float s = bv, sb = bv;
            #pragma unroll
            for (int q = 0; q < R_; ++q) {
                s  = fmaf(sF[t][q],  wdt[q], s);
                sb = fmaf(sBb[t][q], wdt[q], sb);
            }
            const float dl  = softplusf(s);
            const float dlb = softplusf(sb);
            g_delta[(b*L_ + l0 + t)*D_ + d] = dl;   // for correct2 slow path
            const float xv = x_ptr[t*D_];
            const float xr = xr_ptr[-t*D_];
            const float c1 = dl*xv, c2 = dlb*xr;
            float y = 0.f;
            #pragma unroll
            for (int n = 0; n < N_; ++n) {
                const float e = __expf(dl * a[n]);
                h[n] = fmaf(e, h[n], fmaf(c1, sF[t][16+n], c2 * sF[t][32+n]));
                y    = fmaf(h[n], sF[t][48+n], y);
                p[n] *= e;
            }
            y_ptr[t*D_] = fmaf(xv + xr, dsk, y);
        }
        #pragma unroll
        for (int n = 0; n < N_; ++n) { Pp[n*D_] = p[n]; Hp[n*D_] = h[n]; }
    }
}

// ---------------------------------------------------------------------------
// Kernel 3: combine — segmented affine scan (unchanged).
// ---------------------------------------------------------------------------
__global__ __launch_bounds__(512) void combine_kernel()
{
    const int bn = blockIdx.x;
    const int b = bn >> 4;
    const int n = bn & 15;
    const int seg = threadIdx.x >> 7;
    const int dp  = threadIdx.x & 127;

    __shared__ ull sP[4][128];
    __shared__ ull sH[4][128];

    const ull* P2 = reinterpret_cast<const ull*>(g_P);
    const ull* H2 = reinterpret_cast<const ull*>(g_H);
    ull* hs2 = reinterpret_cast<ull*>(g_hs);

    const int c0 = seg * SEGC;
    #define CIDX(c) ((((b*NC + (c))*N_) + n)*128 + dp)

    ull Pc = pack2(1.f, 1.f), Hc = 0ull;
    #pragma unroll 4
    for (int i = 0; i < SEGC; ++i) {
        const int idx = CIDX(c0 + i);
        const ull p = P2[idx];
        Pc = mul2(p, Pc);
        Hc = fma2(p, Hc, H2[idx]);
    }
    sP[seg][dp] = Pc;
    sH[seg][dp] = Hc;
    __syncthreads();

    ull h = 0ull;
    #pragma unroll
    for (int t = 0; t < 3; ++t)
        if (t < seg) h = fma2(sP[t][dp], h, sH[t][dp]);

    #pragma unroll 4
    for (int i = 0; i < SEGC; ++i) {
        const int idx = CIDX(c0 + i);
        hs2[idx] = h;
        h = fma2(P2[idx], h, H2[idx]);
    }
    #undef CIDX
}

// ---------------------------------------------------------------------------
// Kernel 4: correct2 — y += pcum^n * hs * C; emits packed y16.
// C sourced from g_P80 cols 48:64.
// ---------------------------------------------------------------------------
__global__ __launch_bounds__(256) void correct2_kernel(
    const float* __restrict__ A_log)
{
    const int bc = blockIdx.x;
    const int b = bc / NC, c = bc - b*NC;
    const int d = threadIdx.x;
    const int l0 = c * CL;

    __shared__ __align__(16) float sC[CL][N_];
    for (int i = d; i < CL*N_; i += 256) {
        int t = i >> 4, j = i & 15;
        sC[t][j] = g_P80[(size_t)(b*L_ + l0 + t)*NP + 48 + j];
    }
    __syncthreads();

    bool fast;
    const float a0 = check_A(A_log, d, fast);
    (void)a0;

    const float* y_ptr  = g_y  + (b*L_ + l0)*D_ + d;
    uint32_t* y16_ptr   = g_y16 + (b*L_ + l0)*D_ + d;
    const float* pc_ptr = g_pc + (b*L_ + l0)*D_ + d;

    if (fast) {
        ull q2[8];
        #pragma unroll
        for (int k = 0; k < 8; ++k) {
            const float qlo = g_hs[((b*NC + c)*N_ + 2*k  )*D_ + d];
            const float qhi = g_hs[((b*NC + c)*N_ + 2*k+1)*D_ + d];
            q2[k] = pack2(qlo, qhi);
        }
        #pragma unroll
        for (int t0 = 0; t0 < CL; t0 += 4) {
            float p1[4], yl[4];
            #pragma unroll
            for (int i = 0; i < 4; ++i) {
                p1[i] = pc_ptr[(t0+i)*D_];
                yl[i] = y_ptr [(t0+i)*D_];
            }
            #pragma unroll
            for (int i = 0; i < 4; ++i) {
                const int t = t0 + i;
                const float psq = p1[i] * p1[i];
                ull pw = pack2(p1[i], psq);
                const ull pstep = pack2(psq, psq);
                const ull* C2 = reinterpret_cast<const ull*>(&sC[t][0]);
                ull corr2 = 0ull;
                #pragma unroll
                for (int k = 0; k < 8; ++k) {
                    corr2 = fma2(mul2(pw, q2[k]), C2[k], corr2);
                    if (k < 7) pw = mul2(pw, pstep);
                }
                float clo, chi; unpack2(corr2, clo, chi);
                y16_ptr[t*D_] = pack_hilo(yl[i] + clo + chi);
            }
        }
    } else {
        float q[N_];
        #pragma unroll
        for (int n = 0; n < N_; ++n)
            q[n] = g_hs[((b*NC + c)*N_ + n)*D_ + d];
        const float* dl_ptr = g_delta + (b*L_ + l0)*D_ + d;
        float a[N_];
        #pragma unroll
        for (int n = 0; n < N_; ++n)
            a[n] = -__expf(__ldg(A_log + d*N_ + n));
        for (int t = 0; t < CL; ++t) {
            const float dl = dl_ptr[t*D_];
            float corr = 0.f;
            #pragma unroll
            for (int n = 0; n < N_; ++n) {
                q[n] *= __expf(dl * a[n]);
                corr = fmaf(q[n], sC[t][n], corr);
            }
            y16_ptr[t*D_] = pack_hilo(y_ptr[t*D_] + corr);
        }
    }
}

// ---------------------------------------------------------------------------
// Kernel 5: out = y @ W_out^T via mma.sync bf16 split, prepacked (unchanged).
// ---------------------------------------------------------------------------
__global__ __launch_bounds__(256) void gemm_mma_kernel(float* __restrict__ out)
{
    extern __shared__ __nv_bfloat16 sm[];
    __nv_bfloat16* sA_hi = sm;
    __nv_bfloat16* sA_lo = sm + 128*GP;
    __nv_bfloat16* sB_hi = sm + 2*128*GP;
    __nv_bfloat16* sB_lo = sm + 3*128*GP;

    const int tid  = threadIdx.x;
    const int wid  = tid >> 5;
    const int lane = tid & 31;
    const int gid  = lane >> 2;
    const int t4   = lane & 3;

    const int j0 = blockIdx.x * 128;
    const int m0 = blockIdx.y * 128;
    const int wm = (wid >> 2) * 64;
    const int wn = (wid & 3) * 32;

    float acc[4][4][4];
    #pragma unroll
    for (int i = 0; i < 4; ++i)
        #pragma unroll
        for (int j = 0; j < 4; ++j)
            #pragma unroll
            for (int q = 0; q < 4; ++q) acc[i][j][q] = 0.f;

    const int lrow = tid >> 5;
    const int lpc  = tid & 31;

    for (int kc = 0; kc < 256; kc += 64) {
        __syncthreads();
        #pragma unroll
        for (int rr = 0; rr < 16; ++rr) {
            const int row = lrow + rr*8;
            const int soff = row*GP + lpc*2;

            const uint2 wa = *reinterpret_cast<const uint2*>(
                g_y16 + (m0 + row)*D_ + kc + lpc*2);
            *reinterpret_cast<uint32_t*>(sA_hi + soff) = __byte_perm(wa.x, wa.y, 0x5410);
            *reinterpret_cast<uint32_t*>(sA_lo + soff) = __byte_perm(wa.x, wa.y, 0x7632);

            const uint2 wb = *reinterpret_cast<const uint2*>(
                g_W16 + (j0 + row)*D_ + kc + lpc*2);
            *reinterpret_cast<uint32_t*>(sB_hi + soff) = __byte_perm(wb.x, wb.y, 0x5410);
            *reinterpret_cast<uint32_t*>(sB_lo + soff) = __byte_perm(wb.x, wb.y, 0x7632);
        }
        __syncthreads();

        #pragma unroll
        for (int ks = 0; ks < 4; ++ks) {
            const int k0 = ks*16;
            uint32_t a_hi[4][4], a_lo[4][4], b_hi[4][2], b_lo[4][2];

            #pragma unroll
            for (int mf = 0; mf < 4; ++mf) {
                const int r0 = wm + mf*16 + gid;
                const int c0 = k0 + t4*2;
                a_hi[mf][0] = *reinterpret_cast<const uint32_t*>(sA_hi + (r0    )*GP + c0    );
                a_hi[mf][1] = *reinterpret_cast<const uint32_t*>(sA_hi + (r0 + 8)*GP + c0    );
                a_hi[mf][2] = *reinterpret_cast<const uint32_t*>(sA_hi + (r0    )*GP + c0 + 8);
                a_hi[mf][3] = *reinterpret_cast<const uint32_t*>(sA_hi + (r0 + 8)*GP + c0 + 8);
                a_lo[mf][0] = *reinterpret_cast<const uint32_t*>(sA_lo + (r0    )*GP + c0    );
                a_lo[mf][1] = *reinterpret_cast<const uint32_t*>(sA_lo + (r0 + 8)*GP + c0    );
                a_lo[mf][2] = *reinterpret_cast<const uint32_t*>(sA_lo + (r0    )*GP + c0 + 8);
                a_lo[mf][3] = *reinterpret_cast<const uint32_t*>(sA_lo + (r0 + 8)*GP + c0 + 8);
            }
            #pragma unroll
            for (int nf = 0; nf < 4; ++nf) {
                const int nr = wn + nf*8 + gid;
                const int c0 = k0 + t4*2;
                b_hi[nf][0] = *reinterpret_cast<const uint32_t*>(sB_hi + nr*GP + c0    );
                b_hi[nf][1] = *reinterpret_cast<const uint32_t*>(sB_hi + nr*GP + c0 + 8);
                b_lo[nf][0] = *reinterpret_cast<const uint32_t*>(sB_lo + nr*GP + c0    );
                b_lo[nf][1] = *reinterpret_cast<const uint32_t*>(sB_lo + nr*GP + c0 + 8);
            }

            #pragma unroll
            for (int mf = 0; mf < 4; ++mf)
                #pragma unroll
                for (int nf = 0; nf < 4; ++nf) {
                    mma_bf16(acc[mf][nf], a_hi[mf], b_hi[nf]);
                    mma_bf16(acc[mf][nf], a_hi[mf], b_lo[nf]);
                    mma_bf16(acc[mf][nf], a_lo[mf], b_hi[nf]);
                }
        }
    }

    #pragma unroll
    for (int mf = 0; mf < 4; ++mf) {
        const int mrow = m0 + wm + mf*16 + gid;
        #pragma unroll
        for (int nf = 0; nf < 4; ++nf) {
            const int ncol = j0 + wn + nf*8 + t4*2;
            *reinterpret_cast<float2*>(out + (size_t)mrow*D_ + ncol) =
                make_float2(acc[mf][nf][0], acc[mf][nf][1]);
            *reinterpret_cast<float2*>(out + (size_t)(mrow + 8)*D_ + ncol) =
                make_float2(acc[mf][nf][2], acc[mf][nf][3]);
        }
    }
}

// ---------------------------------------------------------------------------
extern "C" void kernel_launch(void* const* d_in, const int* in_sizes, int n_in,
                              void* d_out, int out_size)
{
    const float* x     = (const float*)d_in[0];
    const float* Wxp   = (const float*)d_in[1];
    const float* Wxb   = (const float*)d_in[2];
    const float* Wdt   = (const float*)d_in[3];
    const float* bdt   = (const float*)d_in[4];
    const float* A_log = (const float*)d_in[5];
    const float* Dskip = (const float*)d_in[6];
    const float* Wout  = (const float*)d_in[7];
    float* out = (float*)d_out;

    const int GEMM_SMEM = 4 * 128 * GP * (int)sizeof(__nv_bfloat16);  // 73728 B
    cudaFuncSetAttribute(gemm_mma_kernel,
                         cudaFuncAttributeMaxDynamicSharedMemorySize, GEMM_SMEM);
    cudaFuncSetAttribute(projgemm_kernel,
                         cudaFuncAttributeMaxDynamicSharedMemorySize, GEMM_SMEM);

    pack_kernel    <<<384, 256>>>(Wout, Wxp, Wxb);
    projgemm_kernel<<<dim3(1, 128), 256, GEMM_SMEM>>>(x);
    scan_kernel    <<<B_*NC, 256>>>(x, Wdt, bdt, A_log, Dskip);
    combine_kernel <<<B_*N_, 512>>>();
    correct2_kernel<<<B_*NC, 256>>>(A_log);
    gemm_mma_kernel<<<dim3(2, 128), 256, GEMM_SMEM>>>(out);
}

// round 14
// speedup vs baseline: 1.8633x; 1.6191x over previous
#include <cuda_runtime.h>
#include <cuda_bf16.h>
#include <math.h>
#include <stdint.h>

#define B_    8
#define L_    2048
#define D_    256
#define N_    16
#define R_    16
#define CL    32          // scan chunk length
#define NC    (L_/CL)     // 64 chunks
#define SEGC  (NC/4)      // 16 chunks per combine segment
#define NP    80          // projection outputs per row

typedef unsigned long long ull;

// ---------------- scratch (device globals) ----------------
__device__ float    g_P80    [B_*L_*NP];      // all projections (from tensor GEMM)
__device__ float    g_delta  [B_*L_*D_];      // slow-path only
__device__ float    g_pc     [B_*L_*D_];      // cumulative p1 within chunk
__device__ float    g_P      [B_*NC*N_*D_];
__device__ float    g_H      [B_*NC*N_*D_];
__device__ float    g_hs     [B_*NC*N_*D_];
__device__ float    g_y      [B_*L_*D_];      // y_local (pre-correction)
__device__ uint32_t g_y16    [B_*L_*D_];      // final y packed (bf16 hi | lo<<16)
__device__ uint32_t g_W16    [D_*D_];         // W_out packed (bf16 hi | lo<<16)
__device__ uint32_t g_Wall16 [128*D_];        // [Wxp(64);Wxb(16);0(48)] packed

// FAST softplus: MUFU EX2/LG2 path (NOT library log1pf — that costed ~30 µs in R13)
__device__ __forceinline__ float softplusf(float v) {
    return v > 20.0f ? v : __logf(1.0f + __expf(v));
}

__device__ __forceinline__ uint32_t pack_hilo(float v) {
    __nv_bfloat16 h = __float2bfloat16(v);
    __nv_bfloat16 l = __float2bfloat16(v - __bfloat162float(h));
    return (uint32_t)__bfloat16_as_ushort(h) |
           ((uint32_t)__bfloat16_as_ushort(l) << 16);
}

// ---------------- packed f32x2 helpers ----------------
__device__ __forceinline__ ull pack2(float lo, float hi) {
    ull r;
    asm("mov.b64 %0, {%1, %2};" : "=l"(r) : "f"(lo), "f"(hi));
    return r;
}
__device__ __forceinline__ void unpack2(ull v, float& lo, float& hi) {
    asm("mov.b64 {%0, %1}, %2;" : "=f"(lo), "=f"(hi) : "l"(v));
}
__device__ __forceinline__ ull mul2(ull a, ull b) {
    ull d;
    asm("mul.rn.f32x2 %0, %1, %2;" : "=l"(d) : "l"(a), "l"(b));
    return d;
}
__device__ __forceinline__ ull fma2(ull a, ull b, ull c) {
    ull d;
    asm("fma.rn.f32x2 %0, %1, %2, %3;" : "=l"(d) : "l"(a), "l"(b), "l"(c));
    return d;
}
__device__ __forceinline__ void powers16_p2(float p1, ull e2[8]) {
    const float p1sq = p1 * p1;
    e2[0] = pack2(p1, p1sq);
    const ull pstep = pack2(p1sq, p1sq);
    #pragma unroll
    for (int k = 1; k < 8; ++k) e2[k] = mul2(e2[k-1], pstep);
}

__device__ __forceinline__ float check_A(const float* __restrict__ A_log,
                                         int d, bool& fast) {
    float a0 = -__expf(__ldg(A_log + d*N_));
    fast = true;
    #pragma unroll
    for (int n = 1; n < N_; ++n) {
        float an = -__expf(__ldg(A_log + d*N_ + n));
        fast = fast && (fabsf(an - a0*(float)(n+1)) <= 1e-4f*(float)(n+1));
    }
    return a0;
}

// ---------------------------------------------------------------------------
// Kernel 0: pack W_out (65536) + Wall (128x256, zero-padded) to bf16 hi/lo.
// ---------------------------------------------------------------------------
__global__ __launch_bounds__(256) void pack_kernel(
    const float* __restrict__ Wout, const float* __restrict__ Wxp,
    const float* __restrict__ Wxb)
{
    const int i = blockIdx.x*256 + threadIdx.x;
    if (i < D_*D_) {
        g_W16[i] = pack_hilo(Wout[i]);
    } else {
        const int k = i - D_*D_;        // 0 .. 32767
        const int row = k >> 8, col = k & 255;
        float v = 0.f;
        if (row < 64)       v = Wxp[row*D_ + col];
        else if (row < 80)  v = Wxb[(row - 64)*D_ + col];
        g_Wall16[k] = pack_hilo(v);
    }
}

// ---------------------------------------------------------------------------
// Kernel 1: projgemm — P80 = x @ Wall^T via mma.sync bf16 split (unchanged).
// ---------------------------------------------------------------------------
#define GP 72   // smem pitch in bf16 elements

__device__ __forceinline__ void mma_bf16(float dd[4],
                                         const uint32_t a[4],
                                         const uint32_t b[2]) {
    asm volatile(
        "mma.sync.aligned.m16n8k16.row.col.f32.bf16.bf16.f32 "
        "{%0,%1,%2,%3}, {%4,%5,%6,%7}, {%8,%9}, {%0,%1,%2,%3};"
        : "+f"(dd[0]), "+f"(dd[1]), "+f"(dd[2]), "+f"(dd[3])
        : "r"(a[0]), "r"(a[1]), "r"(a[2]), "r"(a[3]), "r"(b[0]), "r"(b[1]));
}

__global__ __launch_bounds__(256) void projgemm_kernel(const float* __restrict__ x)
{
    extern __shared__ __nv_bfloat16 sm[];
    __nv_bfloat16* sA_hi = sm;
    __nv_bfloat16* sA_lo = sm + 128*GP;
    __nv_bfloat16* sB_hi = sm + 2*128*GP;
    __nv_bfloat16* sB_lo = sm + 3*128*GP;

    const int tid  = threadIdx.x;
    const int wid  = tid >> 5;
    const int lane = tid & 31;
    const int gid  = lane >> 2;
    const int t4   = lane & 3;

    const int m0 = blockIdx.y * 128;
    const int wm = (wid >> 2) * 64;
    const int wn = (wid & 3) * 32;

    float acc[4][4][4];
    #pragma unroll
    for (int i = 0; i < 4; ++i)
        #pragma unroll
        for (int j = 0; j < 4; ++j)
            #pragma unroll
            for (int q = 0; q < 4; ++q) acc[i][j][q] = 0.f;

    const int lrow = tid >> 5;
    const int lpc  = tid & 31;

    for (int kc = 0; kc < 256; kc += 64) {
        __syncthreads();
        #pragma unroll
        for (int rr = 0; rr < 16; ++rr) {
            const int row = lrow + rr*8;
            const int soff = row*GP + lpc*2;

            const float2 va = *reinterpret_cast<const float2*>(
                x + (size_t)(m0 + row)*D_ + kc + lpc*2);
            __nv_bfloat16 ahx = __float2bfloat16(va.x);
            __nv_bfloat16 ahy = __float2bfloat16(va.y);
            __nv_bfloat16 alx = __float2bfloat16(va.x - __bfloat162float(ahx));
            __nv_bfloat16 aly = __float2bfloat16(va.y - __bfloat162float(ahy));
            *reinterpret_cast<__nv_bfloat162*>(sA_hi + soff) = __nv_bfloat162(ahx, ahy);
            *reinterpret_cast<__nv_bfloat162*>(sA_lo + soff) = __nv_bfloat162(alx, aly);

            const uint2 wb = *reinterpret_cast<const uint2*>(
                g_Wall16 + row*D_ + kc + lpc*2);
            *reinterpret_cast<uint32_t*>(sB_hi + soff) = __byte_perm(wb.x, wb.y, 0x5410);
            *reinterpret_cast<uint32_t*>(sB_lo + soff) = __byte_perm(wb.x, wb.y, 0x7632);
        }
        __syncthreads();

        #pragma unroll
        for (int ks = 0; ks < 4; ++ks) {
            const int k0 = ks*16;
            uint32_t a_hi[4][4], a_lo[4][4], b_hi[4][2], b_lo[4][2];

            #pragma unroll
            for (int mf = 0; mf < 4; ++mf) {
                const int r0 = wm + mf*16 + gid;
                const int c0 = k0 + t4*2;
                a_hi[mf][0] = *reinterpret_cast<const uint32_t*>(sA_hi + (r0    )*GP + c0    );
                a_hi[mf][1] = *reinterpret_cast<const uint32_t*>(sA_hi + (r0 + 8)*GP + c0    );
                a_hi[mf][2] = *reinterpret_cast<const uint32_t*>(sA_hi + (r0    )*GP + c0 + 8);
                a_hi[mf][3] = *reinterpret_cast<const uint32_t*>(sA_hi + (r0 + 8)*GP + c0 + 8);
                a_lo[mf][0] = *reinterpret_cast<const uint32_t*>(sA_lo + (r0    )*GP + c0    );
                a_lo[mf][1] = *reinterpret_cast<const uint32_t*>(sA_lo + (r0 + 8)*GP + c0    );
                a_lo[mf][2] = *reinterpret_cast<const uint32_t*>(sA_lo + (r0    )*GP + c0 + 8);
                a_lo[mf][3] = *reinterpret_cast<const uint32_t*>(sA_lo + (r0 + 8)*GP + c0 + 8);
            }
            #pragma unroll
            for (int nf = 0; nf < 4; ++nf) {
                const int nr = wn + nf*8 + gid;
                const int c0 = k0 + t4*2;
                b_hi[nf][0] = *reinterpret_cast<const uint32_t*>(sB_hi + nr*GP + c0    );
                b_hi[nf][1] = *reinterpret_cast<const uint32_t*>(sB_hi + nr*GP + c0 + 8);
                b_lo[nf][0] = *reinterpret_cast<const uint32_t*>(sB_lo + nr*GP + c0    );
                b_lo[nf][1] = *reinterpret_cast<const uint32_t*>(sB_lo + nr*GP + c0 + 8);
            }

            #pragma unroll
            for (int mf = 0; mf < 4; ++mf)
                #pragma unroll
                for (int nf = 0; nf < 4; ++nf) {
                    mma_bf16(acc[mf][nf], a_hi[mf], b_hi[nf]);
                    mma_bf16(acc[mf][nf], a_hi[mf], b_lo[nf]);
                    mma_bf16(acc[mf][nf], a_lo[mf], b_hi[nf]);
                }
        }
    }

    #pragma unroll
    for (int mf = 0; mf < 4; ++mf) {
        const int mrow = m0 + wm + mf*16 + gid;
        #pragma unroll
        for (int nf = 0; nf < 4; ++nf) {
            const int ncol = wn + nf*8 + t4*2;
            if (ncol < NP) {
                *reinterpret_cast<float2*>(g_P80 + (size_t)mrow*NP + ncol) =
                    make_float2(acc[mf][nf][0], acc[mf][nf][1]);
                *reinterpret_cast<float2*>(g_P80 + (size_t)(mrow + 8)*NP + ncol) =
                    make_float2(acc[mf][nf][2], acc[mf][nf][3]);
            }
        }
    }
}

// ---------------------------------------------------------------------------
// Kernel 2: scan — per chunk; dt-dots from staged P80, local recurrence.
// ---------------------------------------------------------------------------
__global__ __launch_bounds__(256) void scan_kernel(
    const float* __restrict__ x, const float* __restrict__ Wdt,
    const float* __restrict__ bdt, const float* __restrict__ A_log,
    const float* __restrict__ Dskip)
{
    const int bc = blockIdx.x;
    const int b = bc / NC, c = bc - b*NC;
    const int d = threadIdx.x;
    const int l0 = c * CL;

    __shared__ __align__(16) float sF[CL][64];
    __shared__ __align__(16) float sBb[CL][16];

    for (int i = d; i < CL*64; i += 256) {
        const int r = i >> 6, col = i & 63;
        sF[r][col] = g_P80[(size_t)(b*L_ + l0 + r)*NP + col];
    }
    for (int i = d; i < CL*16; i += 256) {
        const int r = i >> 4, col = i & 15;
        sBb[r][col] = g_P80[(size_t)(b*L_ + (L_ - 1 - (l0 + r)))*NP + 64 + col];
    }
    __syncthreads();

    float wdt[R_];
    #pragma unroll
    for (int q = 0; q < R_; ++q) wdt[q] = __ldg(Wdt + d*R_ + q);
    const float bv  = bdt[d];
    const float dsk = Dskip[d];
    bool fast;
    const float a0 = check_A(A_log, d, fast);

    const float* x_ptr  = x + (b*L_ + l0)*D_ + d;
    const float* xr_ptr = x + (b*L_ + (L_ - 1 - l0))*D_ + d;
    float* y_ptr  = g_y  + (b*L_ + l0)*D_ + d;
    float* pc_ptr = g_pc + (b*L_ + l0)*D_ + d;
    float* Pp = g_P + ((b*NC + c)*N_)*D_ + d;
    float* Hp = g_H + ((b*NC + c)*N_)*D_ + d;

    if (fast) {
        ull h2[8];
        #pragma unroll
        for (int k = 0; k < 8; ++k) h2[k] = 0ull;
        float p1 = 1.f;

        #pragma unroll
        for (int t0 = 0; t0 < CL; t0 += 4) {
            float xv[4], xr[4];
            #pragma unroll
            for (int i = 0; i < 4; ++i) {
                xv[i] = x_ptr [(t0+i)*D_];
                xr[i] = xr_ptr[-(t0+i)*D_];
            }
            #pragma unroll
            for (int i = 0; i < 4; ++i) {
                const int t = t0 + i;
                const float2* qa = reinterpret_cast<const float2*>(&sF[t][0]);
                const float2* qb = reinterpret_cast<const float2*>(&sBb[t][0]);
                float s0 = bv, s1 = 0.f, u0 = bv, u1 = 0.f;
                #pragma unroll
                for (int q = 0; q < 8; ++q) {
                    const float2 av = qa[q], bw = qb[q];
                    s0 = fmaf(av.x, wdt[2*q],   s0);
                    s1 = fmaf(av.y, wdt[2*q+1], s1);
                    u0 = fmaf(bw.x, wdt[2*q],   u0);
                    u1 = fmaf(bw.y, wdt[2*q+1], u1);
                }
                const float dl  = softplusf(s0 + s1);
                const float dlb = softplusf(u0 + u1);

                const float e1 = __expf(dl * a0);
                const float e1sq = e1 * e1;
                ull e = pack2(e1, e1sq);
                const ull estep = pack2(e1sq, e1sq);
                const float c1 = dl * xv[i], c2 = dlb * xr[i];
                const ull c1p = pack2(c1, c1);
                const ull c2p = pack2(c2, c2);
                ull y2 = 0ull;
                const ull* Bf2 = reinterpret_cast<const ull*>(&sF[t][16]);
                const ull* Bb2 = reinterpret_cast<const ull*>(&sF[t][32]);
                const ull* C2  = reinterpret_cast<const ull*>(&sF[t][48]);
                #pragma unroll
                for (int k = 0; k < 8; ++k) {
                    const ull du = fma2(c1p, Bf2[k], mul2(c2p, Bb2[k]));
                    h2[k] = fma2(e, h2[k], du);
                    y2    = fma2(h2[k], C2[k], y2);
                    if (k < 7) e = mul2(e, estep);
                }
                p1 *= e1;
                float ylo, yhi; unpack2(y2, ylo, yhi);
                y_ptr [t*D_] = fmaf(xv[i] + xr[i], dsk, ylo + yhi);
                pc_ptr[t*D_] = p1;
            }
        }
        ull pw2[8]; powers16_p2(p1, pw2);
        #pragma unroll
        for (int k = 0; k < 8; ++k) {
            float plo, phi; unpack2(pw2[k], plo, phi);
            float hlo, hhi; unpack2(h2[k], hlo, hhi);
            Pp[(2*k  )*D_] = plo;  Pp[(2*k+1)*D_] = phi;
            Hp[(2*k  )*D_] = hlo;  Hp[(2*k+1)*D_] = hhi;
        }
    } else {
        float h[N_], a[N_], p[N_];
        #pragma unroll
        for (int n = 0; n < N_; ++n) {
            a[n] = -__expf(__ldg(A_log + d*N_ + n));
            p[n] = 1.f;
            h[n] = 0.f;
        }
        for (int t = 0; t < CL; ++t) {
            float s = bv, sb = bv;
            #pragma unroll
            for (int q = 0; q < R_; ++q) {
                s  = fmaf(sF[t][q],  wdt[q], s);
                sb = fmaf(sBb[t][q], wdt[q], sb);
            }
            const float dl  = softplusf(s);
            const float dlb = softplusf(sb);
            g_delta[(b*L_ + l0 + t)*D_ + d] = dl;
            const float xv = x_ptr[t*D_];
            const float xr = xr_ptr[-t*D_];
            const float c1 = dl*xv, c2 = dlb*xr;
            float y = 0.f;
            #pragma unroll
            for (int n = 0; n < N_; ++n) {
                const float e = __expf(dl * a[n]);
                h[n] = fmaf(e, h[n], fmaf(c1, sF[t][16+n], c2 * sF[t][32+n]));
                y    = fmaf(h[n], sF[t][48+n], y);
                p[n] *= e;
            }
            y_ptr[t*D_] = fmaf(xv + xr, dsk, y);
        }
        #pragma unroll
        for (int n = 0; n < N_; ++n) { Pp[n*D_] = p[n]; Hp[n*D_] = h[n]; }
    }
}

// ---------------------------------------------------------------------------
// Kernel 3: combine — segmented affine scan (unchanged).
// ---------------------------------------------------------------------------
__global__ __launch_bounds__(512) void combine_kernel()
{
    const int bn = blockIdx.x;
    const int b = bn >> 4;
    const int n = bn & 15;
    const int seg = threadIdx.x >> 7;
    const int dp  = threadIdx.x & 127;

    __shared__ ull sP[4][128];
    __shared__ ull sH[4][128];

    const ull* P2 = reinterpret_cast<const ull*>(g_P);
    const ull* H2 = reinterpret_cast<const ull*>(g_H);
    ull* hs2 = reinterpret_cast<ull*>(g_hs);

    const int c0 = seg * SEGC;
    #define CIDX(c) ((((b*NC + (c))*N_) + n)*128 + dp)

    ull Pc = pack2(1.f, 1.f), Hc = 0ull;
    #pragma unroll 4
    for (int i = 0; i < SEGC; ++i) {
        const int idx = CIDX(c0 + i);
        const ull p = P2[idx];
        Pc = mul2(p, Pc);
        Hc = fma2(p, Hc, H2[idx]);
    }
    sP[seg][dp] = Pc;
    sH[seg][dp] = Hc;
    __syncthreads();

    ull h = 0ull;
    #pragma unroll
    for (int t = 0; t < 3; ++t)
        if (t < seg) h = fma2(sP[t][dp], h, sH[t][dp]);

    #pragma unroll 4
    for (int i = 0; i < SEGC; ++i) {
        const int idx = CIDX(c0 + i);
        hs2[idx] = h;
        h = fma2(P2[idx], h, H2[idx]);
    }
    #undef CIDX
}

// ---------------------------------------------------------------------------
// Kernel 4: correct2 — y += pcum^n * hs * C; emits packed y16.
// ---------------------------------------------------------------------------
__global__ __launch_bounds__(256) void correct2_kernel(
    const float* __restrict__ A_log)
{
    const int bc = blockIdx.x;
    const int b = bc / NC, c = bc - b*NC;
    const int d = threadIdx.x;
    const int l0 = c * CL;

    __shared__ __align__(16) float sC[CL][N_];
    for (int i = d; i < CL*N_; i += 256) {
        int t = i >> 4, j = i & 15;
        sC[t][j] = g_P80[(size_t)(b*L_ + l0 + t)*NP + 48 + j];
    }
    __syncthreads();

    bool fast;
    const float a0 = check_A(A_log, d, fast);
    (void)a0;

    const float* y_ptr  = g_y  + (b*L_ + l0)*D_ + d;
    uint32_t* y16_ptr   = g_y16 + (b*L_ + l0)*D_ + d;
    const float* pc_ptr = g_pc + (b*L_ + l0)*D_ + d;

    if (fast) {
        ull q2[8];
        #pragma unroll
        for (int k = 0; k < 8; ++k) {
            const float qlo = g_hs[((b*NC + c)*N_ + 2*k  )*D_ + d];
            const float qhi = g_hs[((b*NC + c)*N_ + 2*k+1)*D_ + d];
            q2[k] = pack2(qlo, qhi);
        }
        #pragma unroll
        for (int t0 = 0; t0 < CL; t0 += 4) {
            float p1[4], yl[4];
            #pragma unroll
            for (int i = 0; i < 4; ++i) {
                p1[i] = pc_ptr[(t0+i)*D_];
                yl[i] = y_ptr [(t0+i)*D_];
            }
            #pragma unroll
            for (int i = 0; i < 4; ++i) {
                const int t = t0 + i;
                const float psq = p1[i] * p1[i];
                ull pw = pack2(p1[i], psq);
                const ull pstep = pack2(psq, psq);
                const ull* C2 = reinterpret_cast<const ull*>(&sC[t][0]);
                ull corr2 = 0ull;
                #pragma unroll
                for (int k = 0; k < 8; ++k) {
                    corr2 = fma2(mul2(pw, q2[k]), C2[k], corr2);
                    if (k < 7) pw = mul2(pw, pstep);
                }
                float clo, chi; unpack2(corr2, clo, chi);
                y16_ptr[t*D_] = pack_hilo(yl[i] + clo + chi);
            }
        }
    } else {
        float q[N_];
        #pragma unroll
        for (int n = 0; n < N_; ++n)
            q[n] = g_hs[((b*NC + c)*N_ + n)*D_ + d];
        const float* dl_ptr = g_delta + (b*L_ + l0)*D_ + d;
        float a[N_];
        #pragma unroll
        for (int n = 0; n < N_; ++n)
            a[n] = -__expf(__ldg(A_log + d*N_ + n));
        for (int t = 0; t < CL; ++t) {
            const float dl = dl_ptr[t*D_];
            float corr = 0.f;
            #pragma unroll
            for (int n = 0; n < N_; ++n) {
                q[n] *= __expf(dl * a[n]);
                corr = fmaf(q[n], sC[t][n], corr);
            }
            y16_ptr[t*D_] = pack_hilo(y_ptr[t*D_] + corr);
        }
    }
}

// ---------------------------------------------------------------------------
// Kernel 5: out = y @ W_out^T via mma.sync bf16 split, prepacked (unchanged).
// ---------------------------------------------------------------------------
__global__ __launch_bounds__(256) void gemm_mma_kernel(float* __restrict__ out)
{
    extern __shared__ __nv_bfloat16 sm[];
    __nv_bfloat16* sA_hi = sm;
    __nv_bfloat16* sA_lo = sm + 128*GP;
    __nv_bfloat16* sB_hi = sm + 2*128*GP;
    __nv_bfloat16* sB_lo = sm + 3*128*GP;

    const int tid  = threadIdx.x;
    const int wid  = tid >> 5;
    const int lane = tid & 31;
    const int gid  = lane >> 2;
    const int t4   = lane & 3;

    const int j0 = blockIdx.x * 128;
    const int m0 = blockIdx.y * 128;
    const int wm = (wid >> 2) * 64;
    const int wn = (wid & 3) * 32;

    float acc[4][4][4];
    #pragma unroll
    for (int i = 0; i < 4; ++i)
        #pragma unroll
        for (int j = 0; j < 4; ++j)
            #pragma unroll
            for (int q = 0; q < 4; ++q) acc[i][j][q] = 0.f;

    const int lrow = tid >> 5;
    const int lpc  = tid & 31;

    for (int kc = 0; kc < 256; kc += 64) {
        __syncthreads();
        #pragma unroll
        for (int rr = 0; rr < 16; ++rr) {
            const int row = lrow + rr*8;
            const int soff = row*GP + lpc*2;

            const uint2 wa = *reinterpret_cast<const uint2*>(
                g_y16 + (m0 + row)*D_ + kc + lpc*2);
            *reinterpret_cast<uint32_t*>(sA_hi + soff) = __byte_perm(wa.x, wa.y, 0x5410);
            *reinterpret_cast<uint32_t*>(sA_lo + soff) = __byte_perm(wa.x, wa.y, 0x7632);

            const uint2 wb = *reinterpret_cast<const uint2*>(
                g_W16 + (j0 + row)*D_ + kc + lpc*2);
            *reinterpret_cast<uint32_t*>(sB_hi + soff) = __byte_perm(wb.x, wb.y, 0x5410);
            *reinterpret_cast<uint32_t*>(sB_lo + soff) = __byte_perm(wb.x, wb.y, 0x7632);
        }
        __syncthreads();

        #pragma unroll
        for (int ks = 0; ks < 4; ++ks) {
            const int k0 = ks*16;
            uint32_t a_hi[4][4], a_lo[4][4], b_hi[4][2], b_lo[4][2];

            #pragma unroll
            for (int mf = 0; mf < 4; ++mf) {
                const int r0 = wm + mf*16 + gid;
                const int c0 = k0 + t4*2;
                a_hi[mf][0] = *reinterpret_cast<const uint32_t*>(sA_hi + (r0    )*GP + c0    );
                a_hi[mf][1] = *reinterpret_cast<const uint32_t*>(sA_hi + (r0 + 8)*GP + c0    );
                a_hi[mf][2] = *reinterpret_cast<const uint32_t*>(sA_hi + (r0    )*GP + c0 + 8);
                a_hi[mf][3] = *reinterpret_cast<const uint32_t*>(sA_hi + (r0 + 8)*GP + c0 + 8);
                a_lo[mf][0] = *reinterpret_cast<const uint32_t*>(sA_lo + (r0    )*GP + c0    );
                a_lo[mf][1] = *reinterpret_cast<const uint32_t*>(sA_lo + (r0 + 8)*GP + c0    );
                a_lo[mf][2] = *reinterpret_cast<const uint32_t*>(sA_lo + (r0    )*GP + c0 + 8);
                a_lo[mf][3] = *reinterpret_cast<const uint32_t*>(sA_lo + (r0 + 8)*GP + c0 + 8);
            }
            #pragma unroll
            for (int nf = 0; nf < 4; ++nf) {
                const int nr = wn + nf*8 + gid;
                const int c0 = k0 + t4*2;
                b_hi[nf][0] = *reinterpret_cast<const uint32_t*>(sB_hi + nr*GP + c0    );
                b_hi[nf][1] = *reinterpret_cast<const uint32_t*>(sB_hi + nr*GP + c0 + 8);
                b_lo[nf][0] = *reinterpret_cast<const uint32_t*>(sB_lo + nr*GP + c0    );
                b_lo[nf][1] = *reinterpret_cast<const uint32_t*>(sB_lo + nr*GP + c0 + 8);
            }

            #pragma unroll
            for (int mf = 0; mf < 4; ++mf)
                #pragma unroll
                for (int nf = 0; nf < 4; ++nf) {
                    mma_bf16(acc[mf][nf], a_hi[mf], b_hi[nf]);
                    mma_bf16(acc[mf][nf], a_hi[mf], b_lo[nf]);
                    mma_bf16(acc[mf][nf], a_lo[mf], b_hi[nf]);
                }
        }
    }

    #pragma unroll
    for (int mf = 0; mf < 4; ++mf) {
        const int mrow = m0 + wm + mf*16 + gid;
        #pragma unroll
        for (int nf = 0; nf < 4; ++nf) {
            const int ncol = j0 + wn + nf*8 + t4*2;
            *reinterpret_cast<float2*>(out + (size_t)mrow*D_ + ncol) =
                make_float2(acc[mf][nf][0], acc[mf][nf][1]);
            *reinterpret_cast<float2*>(out + (size_t)(mrow + 8)*D_ + ncol) =
                make_float2(acc[mf][nf][2], acc[mf][nf][3]);
        }
    }
}

// ---------------------------------------------------------------------------
extern "C" void kernel_launch(void* const* d_in, const int* in_sizes, int n_in,
                              void* d_out, int out_size)
{
    const float* x     = (const float*)d_in[0];
    const float* Wxp   = (const float*)d_in[1];
    const float* Wxb   = (const float*)d_in[2];
    const float* Wdt   = (const float*)d_in[3];
    const float* bdt   = (const float*)d_in[4];
    const float* A_log = (const float*)d_in[5];
    const float* Dskip = (const float*)d_in[6];
    const float* Wout  = (const float*)d_in[7];
    float* out = (float*)d_out;

    const int GEMM_SMEM = 4 * 128 * GP * (int)sizeof(__nv_bfloat16);  // 73728 B
    cudaFuncSetAttribute(gemm_mma_kernel,
                         cudaFuncAttributeMaxDynamicSharedMemorySize, GEMM_SMEM);
    cudaFuncSetAttribute(projgemm_kernel,
                         cudaFuncAttributeMaxDynamicSharedMemorySize, GEMM_SMEM);

    pack_kernel    <<<384, 256>>>(Wout, Wxp, Wxb);
    projgemm_kernel<<<dim3(1, 128), 256, GEMM_SMEM>>>(x);
    scan_kernel    <<<B_*NC, 256>>>(x, Wdt, bdt, A_log, Dskip);
    combine_kernel <<<B_*N_, 512>>>();
    correct2_kernel<<<B_*NC, 256>>>(A_log);
    gemm_mma_kernel<<<dim3(2, 128), 256, GEMM_SMEM>>>(out);
}

// round 15
// speedup vs baseline: 1.9363x; 1.0392x over previous
#include <cuda_runtime.h>
#include <cuda_bf16.h>
#include <math.h>
#include <stdint.h>

#define B_    8
#define L_    2048
#define D_    256
#define N_    16
#define R_    16
#define CL    32          // scan chunk length
#define NC    (L_/CL)     // 64 chunks
#define NSEG  8           // combine segments
#define SEGC  (NC/NSEG)   // 8 chunks per combine segment
#define NP    80          // projection outputs per row

typedef unsigned long long ull;

// ---------------- scratch (device globals) ----------------
__device__ float    g_P80    [B_*L_*NP];
__device__ float    g_delta  [B_*L_*D_];      // slow-path only
__device__ float    g_pc     [B_*L_*D_];
__device__ float    g_P      [B_*NC*N_*D_];
__device__ float    g_H      [B_*NC*N_*D_];
__device__ float    g_hs     [B_*NC*N_*D_];
__device__ float    g_y      [B_*L_*D_];
__device__ uint32_t g_y16    [B_*L_*D_];
__device__ uint32_t g_W16    [D_*D_];
__device__ uint32_t g_Wall16 [128*D_];

// FAST softplus (MUFU EX2/LG2 — library log1pf cost ~70 µs, R13→R14)
__device__ __forceinline__ float softplusf(float v) {
    return v > 20.0f ? v : __logf(1.0f + __expf(v));
}

__device__ __forceinline__ uint32_t pack_hilo(float v) {
    __nv_bfloat16 h = __float2bfloat16(v);
    __nv_bfloat16 l = __float2bfloat16(v - __bfloat162float(h));
    return (uint32_t)__bfloat16_as_ushort(h) |
           ((uint32_t)__bfloat16_as_ushort(l) << 16);
}

// ---------------- packed f32x2 helpers ----------------
__device__ __forceinline__ ull pack2(float lo, float hi) {
    ull r;
    asm("mov.b64 %0, {%1, %2};" : "=l"(r) : "f"(lo), "f"(hi));
    return r;
}
__device__ __forceinline__ void unpack2(ull v, float& lo, float& hi) {
    asm("mov.b64 {%0, %1}, %2;" : "=f"(lo), "=f"(hi) : "l"(v));
}
__device__ __forceinline__ ull mul2(ull a, ull b) {
    ull d;
    asm("mul.rn.f32x2 %0, %1, %2;" : "=l"(d) : "l"(a), "l"(b));
    return d;
}
__device__ __forceinline__ ull fma2(ull a, ull b, ull c) {
    ull d;
    asm("fma.rn.f32x2 %0, %1, %2, %3;" : "=l"(d) : "l"(a), "l"(b), "l"(c));
    return d;
}
__device__ __forceinline__ void powers16_p2(float p1, ull e2[8]) {
    const float p1sq = p1 * p1;
    e2[0] = pack2(p1, p1sq);
    const ull pstep = pack2(p1sq, p1sq);
    #pragma unroll
    for (int k = 1; k < 8; ++k) e2[k] = mul2(e2[k-1], pstep);
}

__device__ __forceinline__ float check_A(const float* __restrict__ A_log,
                                         int d, bool& fast) {
    float a0 = -__expf(__ldg(A_log + d*N_));
    fast = true;
    #pragma unroll
    for (int n = 1; n < N_; ++n) {
        float an = -__expf(__ldg(A_log + d*N_ + n));
        fast = fast && (fabsf(an - a0*(float)(n+1)) <= 1e-4f*(float)(n+1));
    }
    return a0;
}

// ---------------------------------------------------------------------------
// Kernel 0: pack W_out + Wall (zero-padded) to bf16 hi/lo.
// ---------------------------------------------------------------------------
__global__ __launch_bounds__(256) void pack_kernel(
    const float* __restrict__ Wout, const float* __restrict__ Wxp,
    const float* __restrict__ Wxb)
{
    const int i = blockIdx.x*256 + threadIdx.x;
    if (i < D_*D_) {
        g_W16[i] = pack_hilo(Wout[i]);
    } else {
        const int k = i - D_*D_;
        const int row = k >> 8, col = k & 255;
        float v = 0.f;
        if (row < 64)       v = Wxp[row*D_ + col];
        else if (row < 80)  v = Wxb[(row - 64)*D_ + col];
        g_Wall16[k] = pack_hilo(v);
    }
}

// ---------------------------------------------------------------------------
// Kernel 1: projgemm — pipelined (register prefetch of next K chunk).
// ---------------------------------------------------------------------------
#define GP 72   // smem pitch in bf16 elements

__device__ __forceinline__ void mma_bf16(float dd[4],
                                         const uint32_t a[4],
                                         const uint32_t b[2]) {
    asm volatile(
        "mma.sync.aligned.m16n8k16.row.col.f32.bf16.bf16.f32 "
        "{%0,%1,%2,%3}, {%4,%5,%6,%7}, {%8,%9}, {%0,%1,%2,%3};"
        : "+f"(dd[0]), "+f"(dd[1]), "+f"(dd[2]), "+f"(dd[3])
        : "r"(a[0]), "r"(a[1]), "r"(a[2]), "r"(a[3]), "r"(b[0]), "r"(b[1]));
}

__global__ __launch_bounds__(256) void projgemm_kernel(const float* __restrict__ x)
{
    extern __shared__ __nv_bfloat16 sm[];
    __nv_bfloat16* sA_hi = sm;
    __nv_bfloat16* sA_lo = sm + 128*GP;
    __nv_bfloat16* sB_hi = sm + 2*128*GP;
    __nv_bfloat16* sB_lo = sm + 3*128*GP;

    const int tid  = threadIdx.x;
    const int wid  = tid >> 5;
    const int lane = tid & 31;
    const int gid  = lane >> 2;
    const int t4   = lane & 3;

    const int m0 = blockIdx.y * 128;
    const int wm = (wid >> 2) * 64;
    const int wn = (wid & 3) * 32;

    float acc[4][4][4];
    #pragma unroll
    for (int i = 0; i < 4; ++i)
        #pragma unroll
        for (int j = 0; j < 4; ++j)
            #pragma unroll
            for (int q = 0; q < 4; ++q) acc[i][j][q] = 0.f;

    const int lrow = tid >> 5;
    const int lpc  = tid & 31;

    float2 pa[16];
    uint2  pb[16];
    #pragma unroll
    for (int rr = 0; rr < 16; ++rr) {
        const int row = lrow + rr*8;
        pa[rr] = *reinterpret_cast<const float2*>(x + (size_t)(m0 + row)*D_ + lpc*2);
        pb[rr] = *reinterpret_cast<const uint2*>(g_Wall16 + row*D_ + lpc*2);
    }

    for (int kc = 0; kc < 256; kc += 64) {
        #pragma unroll
        for (int rr = 0; rr < 16; ++rr) {
            const int row = lrow + rr*8;
            const int soff = row*GP + lpc*2;
            __nv_bfloat16 ahx = __float2bfloat16(pa[rr].x);
            __nv_bfloat16 ahy = __float2bfloat16(pa[rr].y);
            __nv_bfloat16 alx = __float2bfloat16(pa[rr].x - __bfloat162float(ahx));
            __nv_bfloat16 aly = __float2bfloat16(pa[rr].y - __bfloat162float(ahy));
            *reinterpret_cast<__nv_bfloat162*>(sA_hi + soff) = __nv_bfloat162(ahx, ahy);
            *reinterpret_cast<__nv_bfloat162*>(sA_lo + soff) = __nv_bfloat162(alx, aly);
            *reinterpret_cast<uint32_t*>(sB_hi + soff) = __byte_perm(pb[rr].x, pb[rr].y, 0x5410);
            *reinterpret_cast<uint32_t*>(sB_lo + soff) = __byte_perm(pb[rr].x, pb[rr].y, 0x7632);
        }
        __syncthreads();

        if (kc < 192) {
            #pragma unroll
            for (int rr = 0; rr < 16; ++rr) {
                const int row = lrow + rr*8;
                pa[rr] = *reinterpret_cast<const float2*>(
                    x + (size_t)(m0 + row)*D_ + kc + 64 + lpc*2);
                pb[rr] = *reinterpret_cast<const uint2*>(
                    g_Wall16 + row*D_ + kc + 64 + lpc*2);
            }
        }

        #pragma unroll
        for (int ks = 0; ks < 4; ++ks) {
            const int k0 = ks*16;
            uint32_t a_hi[4][4], a_lo[4][4], b_hi[4][2], b_lo[4][2];
            #pragma unroll
            for (int mf = 0; mf < 4; ++mf) {
                const int r0 = wm + mf*16 + gid;
                const int c0 = k0 + t4*2;
                a_hi[mf][0] = *reinterpret_cast<const uint32_t*>(sA_hi + (r0    )*GP + c0    );
                a_hi[mf][1] = *reinterpret_cast<const uint32_t*>(sA_hi + (r0 + 8)*GP + c0    );
                a_hi[mf][2] = *reinterpret_cast<const uint32_t*>(sA_hi + (r0    )*GP + c0 + 8);
                a_hi[mf][3] = *reinterpret_cast<const uint32_t*>(sA_hi + (r0 + 8)*GP + c0 + 8);
                a_lo[mf][0] = *reinterpret_cast<const uint32_t*>(sA_lo + (r0    )*GP + c0    );
                a_lo[mf][1] = *reinterpret_cast<const uint32_t*>(sA_lo + (r0 + 8)*GP + c0    );
                a_lo[mf][2] = *reinterpret_cast<const uint32_t*>(sA_lo + (r0    )*GP + c0 + 8);
                a_lo[mf][3] = *reinterpret_cast<const uint32_t*>(sA_lo + (r0 + 8)*GP + c0 + 8);
            }
            #pragma unroll
            for (int nf = 0; nf < 4; ++nf) {
                const int nr = wn + nf*8 + gid;
                const int c0 = k0 + t4*2;
                b_hi[nf][0] = *reinterpret_cast<const uint32_t*>(sB_hi + nr*GP + c0    );
                b_hi[nf][1] = *reinterpret_cast<const uint32_t*>(sB_hi + nr*GP + c0 + 8);
                b_lo[nf][0] = *reinterpret_cast<const uint32_t*>(sB_lo + nr*GP + c0    );
                b_lo[nf][1] = *reinterpret_cast<const uint32_t*>(sB_lo + nr*GP + c0 + 8);
            }
            #pragma unroll
            for (int mf = 0; mf < 4; ++mf)
                #pragma unroll
                for (int nf = 0; nf < 4; ++nf) {
                    mma_bf16(acc[mf][nf], a_hi[mf], b_hi[nf]);
                    mma_bf16(acc[mf][nf], a_hi[mf], b_lo[nf]);
                    mma_bf16(acc[mf][nf], a_lo[mf], b_hi[nf]);
                }
        }
        __syncthreads();
    }

    #pragma unroll
    for (int mf = 0; mf < 4; ++mf) {
        const int mrow = m0 + wm + mf*16 + gid;
        #pragma unroll
        for (int nf = 0; nf < 4; ++nf) {
            const int ncol = wn + nf*8 + t4*2;
            if (ncol < NP) {
                *reinterpret_cast<float2*>(g_P80 + (size_t)mrow*NP + ncol) =
                    make_float2(acc[mf][nf][0], acc[mf][nf][1]);
                *reinterpret_cast<float2*>(g_P80 + (size_t)(mrow + 8)*NP + ncol) =
                    make_float2(acc[mf][nf][2], acc[mf][nf][3]);
            }
        }
    }
}

// ---------------------------------------------------------------------------
// Kernel 2: scan (unchanged from R14).
// ---------------------------------------------------------------------------
__global__ __launch_bounds__(256) void scan_kernel(
    const float* __restrict__ x, const float* __restrict__ Wdt,
    const float* __restrict__ bdt, const float* __restrict__ A_log,
    const float* __restrict__ Dskip)
{
    const int bc = blockIdx.x;
    const int b = bc / NC, c = bc - b*NC;
    const int d = threadIdx.x;
    const int l0 = c * CL;

    __shared__ __align__(16) float sF[CL][64];
    __shared__ __align__(16) float sBb[CL][16];

    for (int i = d; i < CL*64; i += 256) {
        const int r = i >> 6, col = i & 63;
        sF[r][col] = g_P80[(size_t)(b*L_ + l0 + r)*NP + col];
    }
    for (int i = d; i < CL*16; i += 256) {
        const int r = i >> 4, col = i & 15;
        sBb[r][col] = g_P80[(size_t)(b*L_ + (L_ - 1 - (l0 + r)))*NP + 64 + col];
    }
    __syncthreads();

    float wdt[R_];
    #pragma unroll
    for (int q = 0; q < R_; ++q) wdt[q] = __ldg(Wdt + d*R_ + q);
    const float bv  = bdt[d];
    const float dsk = Dskip[d];
    bool fast;
    const float a0 = check_A(A_log, d, fast);

    const float* x_ptr  = x + (b*L_ + l0)*D_ + d;
    const float* xr_ptr = x + (b*L_ + (L_ - 1 - l0))*D_ + d;
    float* y_ptr  = g_y  + (b*L_ + l0)*D_ + d;
    float* pc_ptr = g_pc + (b*L_ + l0)*D_ + d;
    float* Pp = g_P + ((b*NC + c)*N_)*D_ + d;
    float* Hp = g_H + ((b*NC + c)*N_)*D_ + d;

    if (fast) {
        ull h2[8];
        #pragma unroll
        for (int k = 0; k < 8; ++k) h2[k] = 0ull;
        float p1 = 1.f;

        #pragma unroll
        for (int t0 = 0; t0 < CL; t0 += 4) {
            float xv[4], xr[4];
            #pragma unroll
            for (int i = 0; i < 4; ++i) {
                xv[i] = x_ptr [(t0+i)*D_];
                xr[i] = xr_ptr[-(t0+i)*D_];
            }
            #pragma unroll
            for (int i = 0; i < 4; ++i) {
                const int t = t0 + i;
                const float2* qa = reinterpret_cast<const float2*>(&sF[t][0]);
                const float2* qb = reinterpret_cast<const float2*>(&sBb[t][0]);
                float s0 = bv, s1 = 0.f, u0 = bv, u1 = 0.f;
                #pragma unroll
                for (int q = 0; q < 8; ++q) {
                    const float2 av = qa[q], bw = qb[q];
                    s0 = fmaf(av.x, wdt[2*q],   s0);
                    s1 = fmaf(av.y, wdt[2*q+1], s1);
                    u0 = fmaf(bw.x, wdt[2*q],   u0);
                    u1 = fmaf(bw.y, wdt[2*q+1], u1);
                }
                const float dl  = softplusf(s0 + s1);
                const float dlb = softplusf(u0 + u1);

                const float e1 = __expf(dl * a0);
                const float e1sq = e1 * e1;
                ull e = pack2(e1, e1sq);
                const ull estep = pack2(e1sq, e1sq);
                const float c1 = dl * xv[i], c2 = dlb * xr[i];
                const ull c1p = pack2(c1, c1);
                const ull c2p = pack2(c2, c2);
                ull y2 = 0ull;
                const ull* Bf2 = reinterpret_cast<const ull*>(&sF[t][16]);
                const ull* Bb2 = reinterpret_cast<const ull*>(&sF[t][32]);
                const ull* C2  = reinterpret_cast<const ull*>(&sF[t][48]);
                #pragma unroll
                for (int k = 0; k < 8; ++k) {
                    const ull du = fma2(c1p, Bf2[k], mul2(c2p, Bb2[k]));
                    h2[k] = fma2(e, h2[k], du);
                    y2    = fma2(h2[k], C2[k], y2);
                    if (k < 7) e = mul2(e, estep);
                }
                p1 *= e1;
                float ylo, yhi; unpack2(y2, ylo, yhi);
                y_ptr [t*D_] = fmaf(xv[i] + xr[i], dsk, ylo + yhi);
                pc_ptr[t*D_] = p1;
            }
        }
        ull pw2[8]; powers16_p2(p1, pw2);
        #pragma unroll
        for (int k = 0; k < 8; ++k) {
            float plo, phi; unpack2(pw2[k], plo, phi);
            float hlo, hhi; unpack2(h2[k], hlo, hhi);
            Pp[(2*k  )*D_] = plo;  Pp[(2*k+1)*D_] = phi;
            Hp[(2*k  )*D_] = hlo;  Hp[(2*k+1)*D_] = hhi;
        }
    } else {
        float h[N_], a[N_], p[N_];
        #pragma unroll
        for (int n = 0; n < N_; ++n) {
            a[n] = -__expf(__ldg(A_log + d*N_ + n));
            p[n] = 1.f;
            h[n] = 0.f;
        }
        for (int t = 0; t < CL; ++t) {
            float s = bv, sb = bv;
            #pragma unroll
            for (int q = 0; q < R_; ++q) {
                s  = fmaf(sF[t][q],  wdt[q], s);
                sb = fmaf(sBb[t][q], wdt[q], sb);
            }
            const float dl  = softplusf(s);
            const float dlb = softplusf(sb);
            g_delta[(b*L_ + l0 + t)*D_ + d] = dl;
            const float xv = x_ptr[t*D_];
            const float xr = xr_ptr[-t*D_];
            const float c1 = dl*xv, c2 = dlb*xr;
            float y = 0.f;
            #pragma unroll
            for (int n = 0; n < N_; ++n) {
                const float e = __expf(dl * a[n]);
                h[n] = fmaf(e, h[n], fmaf(c1, sF[t][16+n], c2 * sF[t][32+n]));
                y    = fmaf(h[n], sF[t][48+n], y);
                p[n] *= e;
            }
            y_ptr[t*D_] = fmaf(xv + xr, dsk, y);
        }
        #pragma unroll
        for (int n = 0; n < N_; ++n) { Pp[n*D_] = p[n]; Hp[n*D_] = h[n]; }
    }
}

// ---------------------------------------------------------------------------
// Kernel 3: combine — 8 segments x 8 chunks, 1024 threads.
// ---------------------------------------------------------------------------
__global__ __launch_bounds__(1024) void combine_kernel()
{
    const int bn = blockIdx.x;          // 0..127
    const int b = bn >> 4;
    const int n = bn & 15;
    const int seg = threadIdx.x >> 7;   // 0..7
    const int dp  = threadIdx.x & 127;

    __shared__ ull sP[NSEG][128];
    __shared__ ull sH[NSEG][128];

    const ull* P2 = reinterpret_cast<const ull*>(g_P);
    const ull* H2 = reinterpret_cast<const ull*>(g_H);
    ull* hs2 = reinterpret_cast<ull*>(g_hs);

    const int c0 = seg * SEGC;
    #define CIDX(c) ((((b*NC + (c))*N_) + n)*128 + dp)

    ull Pc = pack2(1.f, 1.f), Hc = 0ull;
    #pragma unroll
    for (int i = 0; i < SEGC; ++i) {
        const int idx = CIDX(c0 + i);
        const ull p = P2[idx];
        Pc = mul2(p, Pc);
        Hc = fma2(p, Hc, H2[idx]);
    }
    sP[seg][dp] = Pc;
    sH[seg][dp] = Hc;
    __syncthreads();

    ull h = 0ull;
    #pragma unroll
    for (int t = 0; t < NSEG-1; ++t)
        if (t < seg) h = fma2(sP[t][dp], h, sH[t][dp]);

    #pragma unroll
    for (int i = 0; i < SEGC; ++i) {
        const int idx = CIDX(c0 + i);
        hs2[idx] = h;
        h = fma2(P2[idx], h, H2[idx]);
    }
    #undef CIDX
}

// ---------------------------------------------------------------------------
// Kernel 4: correct2 (unchanged from R14).
// ---------------------------------------------------------------------------
__global__ __launch_bounds__(256) void correct2_kernel(
    const float* __restrict__ A_log)
{
    const int bc = blockIdx.x;
    const int b = bc / NC, c = bc - b*NC;
    const int d = threadIdx.x;
    const int l0 = c * CL;

    __shared__ __align__(16) float sC[CL][N_];
    for (int i = d; i < CL*N_; i += 256) {
        int t = i >> 4, j = i & 15;
        sC[t][j] = g_P80[(size_t)(b*L_ + l0 + t)*NP + 48 + j];
    }
    __syncthreads();

    bool fast;
    const float a0 = check_A(A_log, d, fast);
    (void)a0;

    const float* y_ptr  = g_y  + (b*L_ + l0)*D_ + d;
    uint32_t* y16_ptr   = g_y16 + (b*L_ + l0)*D_ + d;
    const float* pc_ptr = g_pc + (b*L_ + l0)*D_ + d;

    if (fast) {
        ull q2[8];
        #pragma unroll
        for (int k = 0; k < 8; ++k) {
            const float qlo = g_hs[((b*NC + c)*N_ + 2*k  )*D_ + d];
            const float qhi = g_hs[((b*NC + c)*N_ + 2*k+1)*D_ + d];
            q2[k] = pack2(qlo, qhi);
        }
        #pragma unroll
        for (int t0 = 0; t0 < CL; t0 += 4) {
            float p1[4], yl[4];
            #pragma unroll
            for (int i = 0; i < 4; ++i) {
                p1[i] = pc_ptr[(t0+i)*D_];
                yl[i] = y_ptr [(t0+i)*D_];
            }
            #pragma unroll
            for (int i = 0; i < 4; ++i) {
                const int t = t0 + i;
                const float psq = p1[i] * p1[i];
                ull pw = pack2(p1[i], psq);
                const ull pstep = pack2(psq, psq);
                const ull* C2 = reinterpret_cast<const ull*>(&sC[t][0]);
                ull corr2 = 0ull;
                #pragma unroll
                for (int k = 0; k < 8; ++k) {
                    corr2 = fma2(mul2(pw, q2[k]), C2[k], corr2);
                    if (k < 7) pw = mul2(pw, pstep);
                }
                float clo, chi; unpack2(corr2, clo, chi);
                y16_ptr[t*D_] = pack_hilo(yl[i] + clo + chi);
            }
        }
    } else {
        float q[N_];
        #pragma unroll
        for (int n = 0; n < N_; ++n)
            q[n] = g_hs[((b*NC + c)*N_ + n)*D_ + d];
        const float* dl_ptr = g_delta + (b*L_ + l0)*D_ + d;
        float a[N_];
        #pragma unroll
        for (int n = 0; n < N_; ++n)
            a[n] = -__expf(__ldg(A_log + d*N_ + n));
        for (int t = 0; t < CL; ++t) {
            const float dl = dl_ptr[t*D_];
            float corr = 0.f;
            #pragma unroll
            for (int n = 0; n < N_; ++n) {
                q[n] *= __expf(dl * a[n]);
                corr = fmaf(q[n], sC[t][n], corr);
            }
            y16_ptr[t*D_] = pack_hilo(y_ptr[t*D_] + corr);
        }
    }
}

// ---------------------------------------------------------------------------
// Kernel 5: out GEMM — pipelined (register prefetch of next K chunk).
// ---------------------------------------------------------------------------
__global__ __launch_bounds__(256) void gemm_mma_kernel(float* __restrict__ out)
{
    extern __shared__ __nv_bfloat16 sm[];
    __nv_bfloat16* sA_hi = sm;
    __nv_bfloat16* sA_lo = sm + 128*GP;
    __nv_bfloat16* sB_hi = sm + 2*128*GP;
    __nv_bfloat16* sB_lo = sm + 3*128*GP;

    const int tid  = threadIdx.x;
    const int wid  = tid >> 5;
    const int lane = tid & 31;
    const int gid  = lane >> 2;
    const int t4   = lane & 3;

    const int j0 = blockIdx.x * 128;
    const int m0 = blockIdx.y * 128;
    const int wm = (wid >> 2) * 64;
    const int wn = (wid & 3) * 32;

    float acc[4][4][4];
    #pragma unroll
    for (int i = 0; i < 4; ++i)
        #pragma unroll
        for (int j = 0; j < 4; ++j)
            #pragma unroll
            for (int q = 0; q < 4; ++q) acc[i][j][q] = 0.f;

    const int lrow = tid >> 5;
    const int lpc  = tid & 31;

    uint2 pa[16], pb[16];
    #pragma unroll
    for (int rr = 0; rr < 16; ++rr) {
        const int row = lrow + rr*8;
        pa[rr] = *reinterpret_cast<const uint2*>(g_y16 + (m0 + row)*D_ + lpc*2);
        pb[rr] = *reinterpret_cast<const uint2*>(g_W16 + (j0 + row)*D_ + lpc*2);
    }

    for (int kc = 0; kc < 256; kc += 64) {
        #pragma unroll
        for (int rr = 0; rr < 16; ++rr) {
            const int row = lrow + rr*8;
            const int soff = row*GP + lpc*2;
            *reinterpret_cast<uint32_t*>(sA_hi + soff) = __byte_perm(pa[rr].x, pa[rr].y, 0x5410);
            *reinterpret_cast<uint32_t*>(sA_lo + soff) = __byte_perm(pa[rr].x, pa[rr].y, 0x7632);
            *reinterpret_cast<uint32_t*>(sB_hi + soff) = __byte_perm(pb[rr].x, pb[rr].y, 0x5410);
            *reinterpret_cast<uint32_t*>(sB_lo + soff) = __byte_perm(pb[rr].x, pb[rr].y, 0x7632);
        }
        __syncthreads();

        if (kc < 192) {
            #pragma unroll
            for (int rr = 0; rr < 16; ++rr) {
                const int row = lrow + rr*8;
                pa[rr] = *reinterpret_cast<const uint2*>(
                    g_y16 + (m0 + row)*D_ + kc + 64 + lpc*2);
                pb[rr] = *reinterpret_cast<const uint2*>(
                    g_W16 + (j0 + row)*D_ + kc + 64 + lpc*2);
            }
        }

        #pragma unroll
        for (int ks = 0; ks < 4; ++ks) {
            const int k0 = ks*16;
            uint32_t a_hi[4][4], a_lo[4][4], b_hi[4][2], b_lo[4][2];
            #pragma unroll
            for (int mf = 0; mf < 4; ++mf) {
                const int r0 = wm + mf*16 + gid;
                const int c0 = k0 + t4*2;
                a_hi[mf][0] = *reinterpret_cast<const uint32_t*>(sA_hi + (r0    )*GP + c0    );
                a_hi[mf][1] = *reinterpret_cast<const uint32_t*>(sA_hi + (r0 + 8)*GP + c0    );
                a_hi[mf][2] = *reinterpret_cast<const uint32_t*>(sA_hi + (r0    )*GP + c0 + 8);
                a_hi[mf][3] = *reinterpret_cast<const uint32_t*>(sA_hi + (r0 + 8)*GP + c0 + 8);
                a_lo[mf][0] = *reinterpret_cast<const uint32_t*>(sA_lo + (r0    )*GP + c0    );
                a_lo[mf][1] = *reinterpret_cast<const uint32_t*>(sA_lo + (r0 + 8)*GP + c0    );
                a_lo[mf][2] = *reinterpret_cast<const uint32_t*>(sA_lo + (r0    )*GP + c0 + 8);
                a_lo[mf][3] = *reinterpret_cast<const uint32_t*>(sA_lo + (r0 + 8)*GP + c0 + 8);
            }
            #pragma unroll
            for (int nf = 0; nf < 4; ++nf) {
                const int nr = wn + nf*8 + gid;
                const int c0 = k0 + t4*2;
                b_hi[nf][0] = *reinterpret_cast<const uint32_t*>(sB_hi + nr*GP + c0    );
                b_hi[nf][1] = *reinterpret_cast<const uint32_t*>(sB_hi + nr*GP + c0 + 8);
                b_lo[nf][0] = *reinterpret_cast<const uint32_t*>(sB_lo + nr*GP + c0    );
                b_lo[nf][1] = *reinterpret_cast<const uint32_t*>(sB_lo + nr*GP + c0 + 8);
            }
            #pragma unroll
            for (int mf = 0; mf < 4; ++mf)
                #pragma unroll
                for (int nf = 0; nf < 4; ++nf) {
                    mma_bf16(acc[mf][nf], a_hi[mf], b_hi[nf]);
                    mma_bf16(acc[mf][nf], a_hi[mf], b_lo[nf]);
                    mma_bf16(acc[mf][nf], a_lo[mf], b_hi[nf]);
                }
        }
        __syncthreads();
    }

    #pragma unroll
    for (int mf = 0; mf < 4; ++mf) {
        const int mrow = m0 + wm + mf*16 + gid;
        #pragma unroll
        for (int nf = 0; nf < 4; ++nf) {
            const int ncol = j0 + wn + nf*8 + t4*2;
            *reinterpret_cast<float2*>(out + (size_t)mrow*D_ + ncol) =
                make_float2(acc[mf][nf][0], acc[mf][nf][1]);
            *reinterpret_cast<float2*>(out + (size_t)(mrow + 8)*D_ + ncol) =
                make_float2(acc[mf][nf][2], acc[mf][nf][3]);
        }
    }
}

// ---------------------------------------------------------------------------
extern "C" void kernel_launch(void* const* d_in, const int* in_sizes, int n_in,
                              void* d_out, int out_size)
{
    const float* x     = (const float*)d_in[0];
    const float* Wxp   = (const float*)d_in[1];
    const float* Wxb   = (const float*)d_in[2];
    const float* Wdt   = (const float*)d_in[3];
    const float* bdt   = (const float*)d_in[4];
    const float* A_log = (const float*)d_in[5];
    const float* Dskip = (const float*)d_in[6];
    const float* Wout  = (const float*)d_in[7];
    float* out = (float*)d_out;

    const int GEMM_SMEM = 4 * 128 * GP * (int)sizeof(__nv_bfloat16);  // 73728 B
    cudaFuncSetAttribute(gemm_mma_kernel,
                         cudaFuncAttributeMaxDynamicSharedMemorySize, GEMM_SMEM);
    cudaFuncSetAttribute(projgemm_kernel,
                         cudaFuncAttributeMaxDynamicSharedMemorySize, GEMM_SMEM);

    pack_kernel    <<<384, 256>>>(Wout, Wxp, Wxb);
    projgemm_kernel<<<dim3(1, 128), 256, GEMM_SMEM>>>(x);
    scan_kernel    <<<B_*NC, 256>>>(x, Wdt, bdt, A_log, Dskip);
    combine_kernel <<<B_*N_, 1024>>>();
    correct2_kernel<<<B_*NC, 256>>>(A_log);
    gemm_mma_kernel<<<dim3(2, 128), 256, GEMM_SMEM>>>(out);
}